// round 4
// baseline (speedup 1.0000x reference)
#include <cuda_runtime.h>
#include <cuda_bf16.h>

// ---------------------------------------------------------------------------
// RNN: h_t = tanh(X_t @ W_xh + b_h + h_{t-1} @ W_hh) ; y_t = h_t @ W_hq + b_q
// out = [outputs (T*B*O floats) | states (T*B*H floats)]
// T=512 B=64 I=512 H=1024 O=512
//
// R3: recurrence inner loop rebuilt — W amortized over 4 batch rows per LDS
// (kills R2's crossbar bottleneck), f32x2 pairs over adjacent k (no packing),
// double-buffered chunk staging (1 sync/chunk), parallel k-split reduction.
// ---------------------------------------------------------------------------

#define RT 512
#define RB 64
#define RH 1024
#define RI 512
#define RO 512
#define RNCTA 128
#define RCOLS 8
#define CHUNK 128
#define NCHUNK 8
#define HST 132          // chunk row stride (128 + 4 pad), 16B-aligned, odd f4

__device__ unsigned g_bar_count;

// ---- f32x2 packed math helpers ----
__device__ __forceinline__ unsigned long long ffma2(unsigned long long a,
                                                    unsigned long long b,
                                                    unsigned long long c) {
    unsigned long long d;
    asm("fma.rn.f32x2 %0, %1, %2, %3;" : "=l"(d) : "l"(a), "l"(b), "l"(c));
    return d;
}
__device__ __forceinline__ unsigned long long pack2(float lo, float hi) {
    unsigned long long r;
    asm("mov.b64 %0, {%1, %2};" : "=l"(r) : "f"(lo), "f"(hi));
    return r;
}
__device__ __forceinline__ float2 unpack2(unsigned long long v) {
    float lo, hi;
    asm("mov.b64 {%0, %1}, %2;" : "=f"(lo), "=f"(hi) : "l"(v));
    return make_float2(lo, hi);
}
__device__ __forceinline__ float4 ldcg4(const float* p) {
    float4 v;
    asm volatile("ld.global.cg.v4.f32 {%0,%1,%2,%3}, [%4];"
                 : "=f"(v.x), "=f"(v.y), "=f"(v.z), "=f"(v.w) : "l"(p));
    return v;
}

// ---------------------------------------------------------------------------
// Generic fp32 GEMM + bias (unchanged from R2)
// ---------------------------------------------------------------------------
#define GBM 128
#define GBN 128
#define GBK 16

__global__ __launch_bounds__(256) void sgemm_bias(
    const float* __restrict__ A, const float* __restrict__ B,
    const float* __restrict__ bias, float* __restrict__ C,
    int M, int N, int K, int reset_bar)
{
    if (reset_bar && blockIdx.x == 0 && blockIdx.y == 0 && threadIdx.x == 0)
        g_bar_count = 0u;

    __shared__ __align__(16) float As[GBK][GBM + 4];
    __shared__ __align__(16) float Bs[GBK][GBN];

    const int tid = threadIdx.x;
    const int m0 = blockIdx.y * GBM;
    const int n0 = blockIdx.x * GBN;
    const int tm = tid >> 4;
    const int tn = tid & 15;

    unsigned long long acc[8][4];
#pragma unroll
    for (int i = 0; i < 8; i++)
#pragma unroll
        for (int j = 0; j < 4; j++) acc[i][j] = 0ull;

    const int arow = tid >> 2;
    const int acol4 = tid & 3;
    const int brow = tid >> 5;
    const int bcol4 = tid & 31;

    for (int k0 = 0; k0 < K; k0 += GBK) {
#pragma unroll
        for (int p = 0; p < 2; p++) {
            int r = arow + p * 64;
            float4 v = *(const float4*)(A + (size_t)(m0 + r) * K + k0 + acol4 * 4);
            As[acol4 * 4 + 0][r] = v.x;
            As[acol4 * 4 + 1][r] = v.y;
            As[acol4 * 4 + 2][r] = v.z;
            As[acol4 * 4 + 3][r] = v.w;
        }
#pragma unroll
        for (int p = 0; p < 2; p++) {
            int r = brow + p * 8;
            float4 v = *(const float4*)(B + (size_t)(k0 + r) * N + n0 + bcol4 * 4);
            *(float4*)&Bs[r][bcol4 * 4] = v;
        }
        __syncthreads();

#pragma unroll
        for (int kk = 0; kk < GBK; kk++) {
            float4 a0 = *(const float4*)&As[kk][tm * 8];
            float4 a1 = *(const float4*)&As[kk][tm * 8 + 4];
            ulonglong2 b0 = *(const ulonglong2*)&Bs[kk][tn * 8];
            ulonglong2 b1 = *(const ulonglong2*)&Bs[kk][tn * 8 + 4];
            float av[8] = {a0.x, a0.y, a0.z, a0.w, a1.x, a1.y, a1.z, a1.w};
            unsigned long long bv[4] = {b0.x, b0.y, b1.x, b1.y};
#pragma unroll
            for (int i = 0; i < 8; i++) {
                unsigned long long aa = pack2(av[i], av[i]);
#pragma unroll
                for (int j = 0; j < 4; j++) acc[i][j] = ffma2(aa, bv[j], acc[i][j]);
            }
        }
        __syncthreads();
    }

    float bx[8];
#pragma unroll
    for (int c = 0; c < 8; c++) bx[c] = bias[n0 + tn * 8 + c];

#pragma unroll
    for (int i = 0; i < 8; i++) {
        float* cp = C + (size_t)(m0 + tm * 8 + i) * N + n0 + tn * 8;
        float2 v0 = unpack2(acc[i][0]);
        float2 v1 = unpack2(acc[i][1]);
        float2 v2 = unpack2(acc[i][2]);
        float2 v3 = unpack2(acc[i][3]);
        float4 o0 = make_float4(v0.x + bx[0], v0.y + bx[1], v1.x + bx[2], v1.y + bx[3]);
        float4 o1 = make_float4(v2.x + bx[4], v2.y + bx[5], v3.x + bx[6], v3.y + bx[7]);
        *(float4*)cp = o0;
        *(float4*)(cp + 4) = o1;
    }
}

// ---------------------------------------------------------------------------
// Recurrence v3. 128 CTAs x 256 threads, persistent, grid barrier per step.
// CTA owns 8 H-columns. Smem: Wt[8][1024] (j-major W slice, loaded once),
// H0/H1[64][HST] double-buffered chunk staging, Red[256][16] k-reduction pad.
// Thread tid = bg + 16*jp + 32*kq: 4 batch rows (4bg..4bg+3), 4 cols
// (n0+jp*4..+3), 16 k per chunk (kq*16..). acc[i][j] = f32x2 (even-k, odd-k).
// ---------------------------------------------------------------------------
__device__ __forceinline__ void grid_bar(unsigned* epoch, int tid) {
    __threadfence();
    __syncthreads();
    *epoch += 1;
    if (tid == 0) {
        atomicAdd(&g_bar_count, 1u);
        const unsigned tgt = (*epoch) * (unsigned)RNCTA;
        while (*(volatile unsigned*)&g_bar_count < tgt) {}
    }
    __syncthreads();
}

__global__ __launch_bounds__(256) void rnn_recurrence(
    const float* __restrict__ W_hh, float* __restrict__ states)
{
    extern __shared__ float sm[];
    float* Wt  = sm;                         // 8*1024    = 8192 floats
    float* Hb0 = sm + RCOLS * RH;            // 64*132    = 8448
    float* Hb1 = Hb0 + RB * HST;             // 64*132    = 8448
    float* Red = Hb1 + RB * HST;             // 256*16    = 4096

    const int tid = threadIdx.x;
    const int n0 = blockIdx.x * RCOLS;
    const int bg = tid & 15;          // batch group (4 rows)
    const int jp = (tid >> 4) & 1;    // column half (4 cols)
    const int kq = tid >> 5;          // k sixteenth within chunk
    const int w32 = tid >> 5;         // staging: warp id = row group
    const int c4  = tid & 31;         // staging: float4 col in chunk

    // One-time: W_hh column slice -> smem, j-major: Wt[j][k]
    for (int idx = tid; idx < RCOLS * RH; idx += 256) {
        int j = idx & 7, k = idx >> 3;
        Wt[j * RH + k] = W_hh[(size_t)k * RH + n0 + j];
    }
    __syncthreads();

    unsigned epoch = 0;

    // t = 0: h_0 = tanh(xp). 8 cols x 64 b = 128 float4s.
    if (tid < 128) {
        int b = tid >> 1, q = tid & 1;
        float* op = states + (size_t)b * RH + n0 + q * 4;
        float4 xp = *(float4*)op;
        float4 hv;
        hv.x = tanhf(xp.x); hv.y = tanhf(xp.y);
        hv.z = tanhf(xp.z); hv.w = tanhf(xp.w);
        *(float4*)op = hv;
    }
    grid_bar(&epoch, tid);

    const float* wj[4];
#pragma unroll
    for (int j = 0; j < 4; j++) wj[j] = Wt + (jp * 4 + j) * RH;

    for (int t = 1; t < RT; ++t) {
        const float* hprev = states + (size_t)(t - 1) * (RB * RH);

        // prologue: LDG chunk 0 (coalesced 512B/warp, L2-cached)
        float4 stage[8];
#pragma unroll
        for (int i = 0; i < 8; i++)
            stage[i] = ldcg4(hprev + (size_t)(w32 + 8 * i) * RH + c4 * 4);

        unsigned long long acc[4][2][2];   // [i][jpair][--] -> flatten as [4][4]
        unsigned long long a[4][4];
#pragma unroll
        for (int i = 0; i < 4; i++)
#pragma unroll
            for (int j = 0; j < 4; j++) a[i][j] = 0ull;
        (void)acc;

        for (int c = 0; c < NCHUNK; ++c) {
            float* buf = (c & 1) ? Hb1 : Hb0;

            // commit staged chunk c
#pragma unroll
            for (int i = 0; i < 8; i++)
                *(float4*)(buf + (w32 + 8 * i) * HST + c4 * 4) = stage[i];
            __syncthreads();

            // prefetch chunk c+1
            if (c + 1 < NCHUNK) {
                const float* gsrc = hprev + (c + 1) * CHUNK;
#pragma unroll
                for (int i = 0; i < 8; i++)
                    stage[i] = ldcg4(gsrc + (size_t)(w32 + 8 * i) * RH + c4 * 4);
            }

            // compute: 16 k (kq slice) x 4 b x 4 cols
            const int kb = c * CHUNK + kq * 16;   // global k base (for W)
            const int kl = kq * 16;               // local k base (for Hs)
#pragma unroll
            for (int k4 = 0; k4 < 4; k4++) {
                ulonglong2 hh[4];
#pragma unroll
                for (int i = 0; i < 4; i++)
                    hh[i] = *(const ulonglong2*)(buf + (4 * bg + i) * HST + kl + k4 * 4);
                ulonglong2 ww[4];
#pragma unroll
                for (int j = 0; j < 4; j++)
                    ww[j] = *(const ulonglong2*)(wj[j] + kb + k4 * 4);
#pragma unroll
                for (int i = 0; i < 4; i++)
#pragma unroll
                    for (int j = 0; j < 4; j++) {
                        a[i][j] = ffma2(hh[i].x, ww[j].x, a[i][j]);
                        a[i][j] = ffma2(hh[i].y, ww[j].y, a[i][j]);
                    }
            }
            // no trailing sync: next iter writes the other buffer
        }

        // fold f32x2 halves and publish partials: Red[tid][i*4 + j]
#pragma unroll
        for (int i = 0; i < 4; i++) {
            float2 f0 = unpack2(a[i][0]);
            float2 f1 = unpack2(a[i][1]);
            float2 f2 = unpack2(a[i][2]);
            float2 f3 = unpack2(a[i][3]);
            float4 part = make_float4(f0.x + f0.y, f1.x + f1.y,
                                      f2.x + f2.y, f3.x + f3.y);
            *(float4*)(Red + tid * 16 + i * 4) = part;
        }
        __syncthreads();

        // parallel reduction over kq (8) + tanh epilogue: 128 threads
        if (tid < 128) {
            int rbg = tid & 15, rjp = (tid >> 4) & 1, ri = tid >> 5;
            int base = (rbg + 16 * rjp) * 16 + ri * 4;
            float4 s = *(const float4*)(Red + base);
#pragma unroll
            for (int q = 1; q < 8; q++) {
                float4 v = *(const float4*)(Red + base + q * 512);
                s.x += v.x; s.y += v.y; s.z += v.z; s.w += v.w;
            }
            int b = 4 * rbg + ri;
            float* op = states + (size_t)t * (RB * RH) + (size_t)b * RH + n0 + rjp * 4;
            float4 xp = *(float4*)op;
            float4 hv;
            hv.x = tanhf(xp.x + s.x);
            hv.y = tanhf(xp.y + s.y);
            hv.z = tanhf(xp.z + s.z);
            hv.w = tanhf(xp.w + s.w);
            *(float4*)op = hv;
        }

        grid_bar(&epoch, tid);
    }
}

// ---------------------------------------------------------------------------
extern "C" void kernel_launch(void* const* d_in, const int* in_sizes, int n_in,
                              void* d_out, int out_size)
{
    const float* X    = (const float*)d_in[0];
    const float* W_xh = (const float*)d_in[1];
    const float* W_hh = (const float*)d_in[2];
    const float* b_h  = (const float*)d_in[3];
    const float* W_hq = (const float*)d_in[4];
    const float* b_q  = (const float*)d_in[5];

    float* outputs = (float*)d_out;                      // [T*B, O]
    float* states  = outputs + (size_t)RT * RB * RO;     // [T*B, H]

    const int M = RT * RB;  // 32768
    const int rec_smem =
        (RCOLS * RH + 2 * RB * HST + 256 * 16) * (int)sizeof(float);

    cudaFuncSetAttribute(rnn_recurrence,
                         cudaFuncAttributeMaxDynamicSharedMemorySize, rec_smem);

    dim3 blk(256);
    dim3 g1(RH / GBN, M / GBM);   // Xproj: N=1024, K=512 (resets barrier ctr)
    sgemm_bias<<<g1, blk>>>(X, W_xh, b_h, states, M, RH, RI, 1);

    rnn_recurrence<<<RNCTA, 256, rec_smem>>>(W_hh, states);

    dim3 g3(RO / GBN, M / GBM);   // outputs: N=512, K=1024
    sgemm_bias<<<g3, blk>>>(states, W_hq, b_q, outputs, M, RO, RH, 0);
}

// round 5
// speedup vs baseline: 1.1359x; 1.1359x over previous
#include <cuda_runtime.h>
#include <cuda_bf16.h>

// ---------------------------------------------------------------------------
// RNN: h_t = tanh(X_t @ W_xh + b_h + h_{t-1} @ W_hh) ; y_t = h_t @ W_hq + b_q
// out = [outputs (T*B*O floats) | states (T*B*H floats)]
// T=512 B=64 I=512 H=1024 O=512
//
// R4 recurrence: CTA = (32-batch half x 16 cols); .cg loads (L2 not DRAM);
// interleaved W pairs in smem (broadcast reads, no packing); thread owns
// (1 b, 2 cols, full k) -> no reduction; conflict-free h reads (pos=(b+i)%8).
// ---------------------------------------------------------------------------

#define RT 512
#define RB 64
#define RH 1024
#define RI 512
#define RO 512
#define RNCTA 128
#define NJ 16            // cols per CTA
#define NB 32            // batch rows per CTA
#define CHUNK 128
#define NCHUNK 8
#define HST 132          // staging row stride: (b*33 + i) % 8 rotates -> no conflicts

__device__ unsigned g_bar_count;

// ---- f32x2 packed math helpers ----
__device__ __forceinline__ unsigned long long ffma2(unsigned long long a,
                                                    unsigned long long b,
                                                    unsigned long long c) {
    unsigned long long d;
    asm("fma.rn.f32x2 %0, %1, %2, %3;" : "=l"(d) : "l"(a), "l"(b), "l"(c));
    return d;
}
__device__ __forceinline__ unsigned long long pack2(float lo, float hi) {
    unsigned long long r;
    asm("mov.b64 %0, {%1, %2};" : "=l"(r) : "f"(lo), "f"(hi));
    return r;
}
__device__ __forceinline__ float2 unpack2(unsigned long long v) {
    float lo, hi;
    asm("mov.b64 {%0, %1}, %2;" : "=f"(lo), "=f"(hi) : "l"(v));
    return make_float2(lo, hi);
}
__device__ __forceinline__ float4 ldcg4(const float* p) {
    float4 v;
    asm volatile("ld.global.cg.v4.f32 {%0,%1,%2,%3}, [%4];"
                 : "=f"(v.x), "=f"(v.y), "=f"(v.z), "=f"(v.w) : "l"(p));
    return v;
}

// ---------------------------------------------------------------------------
// Generic fp32 GEMM + bias (unchanged; R5 target)
// ---------------------------------------------------------------------------
#define GBM 128
#define GBN 128
#define GBK 16

__global__ __launch_bounds__(256) void sgemm_bias(
    const float* __restrict__ A, const float* __restrict__ B,
    const float* __restrict__ bias, float* __restrict__ C,
    int M, int N, int K, int reset_bar)
{
    if (reset_bar && blockIdx.x == 0 && blockIdx.y == 0 && threadIdx.x == 0)
        g_bar_count = 0u;

    __shared__ __align__(16) float As[GBK][GBM + 4];
    __shared__ __align__(16) float Bs[GBK][GBN];

    const int tid = threadIdx.x;
    const int m0 = blockIdx.y * GBM;
    const int n0 = blockIdx.x * GBN;
    const int tm = tid >> 4;
    const int tn = tid & 15;

    unsigned long long acc[8][4];
#pragma unroll
    for (int i = 0; i < 8; i++)
#pragma unroll
        for (int j = 0; j < 4; j++) acc[i][j] = 0ull;

    const int arow = tid >> 2;
    const int acol4 = tid & 3;
    const int brow = tid >> 5;
    const int bcol4 = tid & 31;

    for (int k0 = 0; k0 < K; k0 += GBK) {
#pragma unroll
        for (int p = 0; p < 2; p++) {
            int r = arow + p * 64;
            float4 v = *(const float4*)(A + (size_t)(m0 + r) * K + k0 + acol4 * 4);
            As[acol4 * 4 + 0][r] = v.x;
            As[acol4 * 4 + 1][r] = v.y;
            As[acol4 * 4 + 2][r] = v.z;
            As[acol4 * 4 + 3][r] = v.w;
        }
#pragma unroll
        for (int p = 0; p < 2; p++) {
            int r = brow + p * 8;
            float4 v = *(const float4*)(B + (size_t)(k0 + r) * N + n0 + bcol4 * 4);
            *(float4*)&Bs[r][bcol4 * 4] = v;
        }
        __syncthreads();

#pragma unroll
        for (int kk = 0; kk < GBK; kk++) {
            float4 a0 = *(const float4*)&As[kk][tm * 8];
            float4 a1 = *(const float4*)&As[kk][tm * 8 + 4];
            ulonglong2 b0 = *(const ulonglong2*)&Bs[kk][tn * 8];
            ulonglong2 b1 = *(const ulonglong2*)&Bs[kk][tn * 8 + 4];
            float av[8] = {a0.x, a0.y, a0.z, a0.w, a1.x, a1.y, a1.z, a1.w};
            unsigned long long bv[4] = {b0.x, b0.y, b1.x, b1.y};
#pragma unroll
            for (int i = 0; i < 8; i++) {
                unsigned long long aa = pack2(av[i], av[i]);
#pragma unroll
                for (int j = 0; j < 4; j++) acc[i][j] = ffma2(aa, bv[j], acc[i][j]);
            }
        }
        __syncthreads();
    }

    float bx[8];
#pragma unroll
    for (int c = 0; c < 8; c++) bx[c] = bias[n0 + tn * 8 + c];

#pragma unroll
    for (int i = 0; i < 8; i++) {
        float* cp = C + (size_t)(m0 + tm * 8 + i) * N + n0 + tn * 8;
        float2 v0 = unpack2(acc[i][0]);
        float2 v1 = unpack2(acc[i][1]);
        float2 v2 = unpack2(acc[i][2]);
        float2 v3 = unpack2(acc[i][3]);
        float4 o0 = make_float4(v0.x + bx[0], v0.y + bx[1], v1.x + bx[2], v1.y + bx[3]);
        float4 o1 = make_float4(v2.x + bx[4], v2.y + bx[5], v3.x + bx[6], v3.y + bx[7]);
        *(float4*)cp = o0;
        *(float4*)(cp + 4) = o1;
    }
}

// ---------------------------------------------------------------------------
// Grid barrier (proven semantics from R2/R3)
// ---------------------------------------------------------------------------
__device__ __forceinline__ void grid_bar(unsigned* epoch, int tid) {
    __threadfence();
    __syncthreads();
    *epoch += 1;
    if (tid == 0) {
        atomicAdd(&g_bar_count, 1u);
        const unsigned tgt = (*epoch) * (unsigned)RNCTA;
        while (*(volatile unsigned*)&g_bar_count < tgt) {}
    }
    __syncthreads();
}

// ---------------------------------------------------------------------------
// Recurrence v4. 128 CTAs x 256 threads, persistent.
// CTA cid: cols n0 = (cid&63)*16, batch half b0 = (cid>>6)*32.
// Smem: Wq[512 kp][8 jg] float4 (interleaved k/j pairs, loaded once, 64KB),
//       Hb0/Hb1[32][HST] double-buffered h staging.
// Thread tid = lb + 32*jg: 1 batch row (b0+lb), 2 cols (n0+2jg, +1), full k.
// acc a0/a1 = f32x2 over (even k, odd k); no cross-thread reduction.
// ---------------------------------------------------------------------------
__global__ __launch_bounds__(256) void rnn_recurrence(
    const float* __restrict__ W_hh, float* __restrict__ states)
{
    extern __shared__ float sm[];
    float* Wq  = sm;                         // 512*8*4 = 16384 floats (64KB)
    float* Hb0 = sm + 16384;                 // 32*132  = 4224
    float* Hb1 = Hb0 + NB * HST;             // 32*132  = 4224

    const int tid = threadIdx.x;
    const int cid = blockIdx.x;
    const int n0 = (cid & 63) * NJ;
    const int b0 = (cid >> 6) * NB;
    const int lb = tid & 31;
    const int jg = tid >> 5;                 // warp id == column pair (uniform/warp)
    const int c4 = tid & 31;

    // One-time: interleave W_hh into Wq[kp][g] = {W[2kp][j],W[2kp+1][j],
    //                                             W[2kp][j+1],W[2kp+1][j+1]}
    for (int idx = tid; idx < 512 * 8; idx += 256) {
        int kp = idx >> 3, g = idx & 7;
        int j = n0 + 2 * g;
        const float* w0 = W_hh + (size_t)(2 * kp) * RH + j;
        const float* w1 = w0 + RH;
        float4 v;
        v.x = w0[0]; v.y = w1[0]; v.z = w0[1]; v.w = w1[1];
        *(float4*)(Wq + (size_t)idx * 4) = v;
    }
    __syncthreads();

    unsigned epoch = 0;

    // t = 0: h_0 = tanh(xp). 32 rows x 16 cols = 256 threads x float2.
    {
        float* op = states + (size_t)(b0 + lb) * RH + n0 + 2 * jg;
        float2 xp = *(float2*)op;
        float2 hv = make_float2(tanhf(xp.x), tanhf(xp.y));
        *(float2*)op = hv;
    }
    grid_bar(&epoch, tid);

    for (int t = 1; t < RT; ++t) {
        const float* hprev = states + (size_t)(t - 1) * (RB * RH) + (size_t)b0 * RH;

        // prologue: stage chunk 0 (coalesced 512B/warp, L2-cached)
        float4 stage[4];
#pragma unroll
        for (int r = 0; r < 4; r++)
            stage[r] = ldcg4(hprev + (size_t)(4 * jg + r) * RH + c4 * 4);

        unsigned long long a0 = 0ull, a1 = 0ull;

        for (int c = 0; c < NCHUNK; ++c) {
            float* buf = (c & 1) ? Hb1 : Hb0;

            // commit staged chunk c (STS.128, pos=(4jg+r)*33+c4 rotates banks)
#pragma unroll
            for (int r = 0; r < 4; r++)
                *(float4*)(buf + (4 * jg + r) * HST + c4 * 4) = stage[r];
            __syncthreads();

            // prefetch chunk c+1
            if (c + 1 < NCHUNK) {
                const float* gs = hprev + (c + 1) * CHUNK;
#pragma unroll
                for (int r = 0; r < 4; r++)
                    stage[r] = ldcg4(gs + (size_t)(4 * jg + r) * RH + c4 * 4);
            }

            // compute: per i -> 4 k values x 2 cols
            const float* hp = buf + lb * HST;
            const float* wp = Wq + c * 2048 + jg * 4;   // Wq[(c*64 + m)][jg]
#pragma unroll 8
            for (int i = 0; i < 32; i++) {
                ulonglong2 h2 = *(const ulonglong2*)(hp + i * 4);
                ulonglong2 w0 = *(const ulonglong2*)(wp + (2 * i) * 32);
                ulonglong2 w1 = *(const ulonglong2*)(wp + (2 * i + 1) * 32);
                a0 = ffma2(h2.x, w0.x, a0);
                a1 = ffma2(h2.x, w0.y, a1);
                a0 = ffma2(h2.y, w1.x, a0);
                a1 = ffma2(h2.y, w1.y, a1);
            }
            // no trailing sync: next iteration writes the other buffer, and
            // buffer reuse (c+2) is fenced by the sync at iteration c+1.
        }

        // epilogue: 2 outputs per thread, in-place
        float2 f0 = unpack2(a0), f1 = unpack2(a1);
        float* op = states + (size_t)t * (RB * RH) + (size_t)(b0 + lb) * RH + n0 + 2 * jg;
        float2 xp = *(float2*)op;
        float2 hv = make_float2(tanhf(xp.x + f0.x + f0.y),
                                tanhf(xp.y + f1.x + f1.y));
        *(float2*)op = hv;

        grid_bar(&epoch, tid);
    }
}

// ---------------------------------------------------------------------------
extern "C" void kernel_launch(void* const* d_in, const int* in_sizes, int n_in,
                              void* d_out, int out_size)
{
    const float* X    = (const float*)d_in[0];
    const float* W_xh = (const float*)d_in[1];
    const float* W_hh = (const float*)d_in[2];
    const float* b_h  = (const float*)d_in[3];
    const float* W_hq = (const float*)d_in[4];
    const float* b_q  = (const float*)d_in[5];

    float* outputs = (float*)d_out;                      // [T*B, O]
    float* states  = outputs + (size_t)RT * RB * RO;     // [T*B, H]

    const int M = RT * RB;  // 32768
    const int rec_smem = (512 * 8 * 4 + 2 * NB * HST) * (int)sizeof(float);

    cudaFuncSetAttribute(rnn_recurrence,
                         cudaFuncAttributeMaxDynamicSharedMemorySize, rec_smem);

    dim3 blk(256);
    dim3 g1(RH / GBN, M / GBM);   // Xproj: N=1024, K=512 (resets barrier ctr)
    sgemm_bias<<<g1, blk>>>(X, W_xh, b_h, states, M, RH, RI, 1);

    rnn_recurrence<<<RNCTA, 256, rec_smem>>>(W_hh, states);

    dim3 g3(RO / GBN, M / GBM);   // outputs: N=512, K=1024
    sgemm_bias<<<g3, blk>>>(states, W_hq, b_q, outputs, M, RO, RH, 0);
}

// round 6
// speedup vs baseline: 1.3508x; 1.1891x over previous
#include <cuda_runtime.h>
#include <cuda_bf16.h>

// ---------------------------------------------------------------------------
// RNN: h_t = tanh(X_t @ W_xh + b_h + h_{t-1} @ W_hh) ; y_t = h_t @ W_hq + b_q
// out = [outputs (T*B*O floats) | states (T*B*H floats)]
// T=512 B=64 I=512 H=1024 O=512
//
// R5 recurrence: 512 thr/CTA (4 warps/SMSP), CTA = 64b x 8cols, thread =
// (b-pair) x (8k-per-chunk slice) x 8 cols -> h read exactly once per element,
// W broadcast halved, FFMA2-pipe-bound (rt-3 RF-bank floor), 16-way k-reduce.
// ---------------------------------------------------------------------------

#define RT 512
#define RB 64
#define RH 1024
#define RI 512
#define RO 512
#define RNCTA 128
#define CHUNK 128
#define NCHUNK 8
#define HST 132          // staging row stride (33 float4s, odd -> rotating banks)

__device__ unsigned g_bar_count;

// ---- f32x2 packed math helpers ----
__device__ __forceinline__ unsigned long long ffma2(unsigned long long a,
                                                    unsigned long long b,
                                                    unsigned long long c) {
    unsigned long long d;
    asm("fma.rn.f32x2 %0, %1, %2, %3;" : "=l"(d) : "l"(a), "l"(b), "l"(c));
    return d;
}
__device__ __forceinline__ unsigned long long pack2(float lo, float hi) {
    unsigned long long r;
    asm("mov.b64 %0, {%1, %2};" : "=l"(r) : "f"(lo), "f"(hi));
    return r;
}
__device__ __forceinline__ float2 unpack2(unsigned long long v) {
    float lo, hi;
    asm("mov.b64 {%0, %1}, %2;" : "=f"(lo), "=f"(hi) : "l"(v));
    return make_float2(lo, hi);
}
__device__ __forceinline__ float4 ldcg4(const float* p) {
    float4 v;
    asm volatile("ld.global.cg.v4.f32 {%0,%1,%2,%3}, [%4];"
                 : "=f"(v.x), "=f"(v.y), "=f"(v.z), "=f"(v.w) : "l"(p));
    return v;
}

// ---------------------------------------------------------------------------
// Generic fp32 GEMM + bias (unchanged; tensorization is the R6 target)
// ---------------------------------------------------------------------------
#define GBM 128
#define GBN 128
#define GBK 16

__global__ __launch_bounds__(256) void sgemm_bias(
    const float* __restrict__ A, const float* __restrict__ B,
    const float* __restrict__ bias, float* __restrict__ C,
    int M, int N, int K, int reset_bar)
{
    if (reset_bar && blockIdx.x == 0 && blockIdx.y == 0 && threadIdx.x == 0)
        g_bar_count = 0u;

    __shared__ __align__(16) float As[GBK][GBM + 4];
    __shared__ __align__(16) float Bs[GBK][GBN];

    const int tid = threadIdx.x;
    const int m0 = blockIdx.y * GBM;
    const int n0 = blockIdx.x * GBN;
    const int tm = tid >> 4;
    const int tn = tid & 15;

    unsigned long long acc[8][4];
#pragma unroll
    for (int i = 0; i < 8; i++)
#pragma unroll
        for (int j = 0; j < 4; j++) acc[i][j] = 0ull;

    const int arow = tid >> 2;
    const int acol4 = tid & 3;
    const int brow = tid >> 5;
    const int bcol4 = tid & 31;

    for (int k0 = 0; k0 < K; k0 += GBK) {
#pragma unroll
        for (int p = 0; p < 2; p++) {
            int r = arow + p * 64;
            float4 v = *(const float4*)(A + (size_t)(m0 + r) * K + k0 + acol4 * 4);
            As[acol4 * 4 + 0][r] = v.x;
            As[acol4 * 4 + 1][r] = v.y;
            As[acol4 * 4 + 2][r] = v.z;
            As[acol4 * 4 + 3][r] = v.w;
        }
#pragma unroll
        for (int p = 0; p < 2; p++) {
            int r = brow + p * 8;
            float4 v = *(const float4*)(B + (size_t)(k0 + r) * N + n0 + bcol4 * 4);
            *(float4*)&Bs[r][bcol4 * 4] = v;
        }
        __syncthreads();

#pragma unroll
        for (int kk = 0; kk < GBK; kk++) {
            float4 a0 = *(const float4*)&As[kk][tm * 8];
            float4 a1 = *(const float4*)&As[kk][tm * 8 + 4];
            ulonglong2 b0 = *(const ulonglong2*)&Bs[kk][tn * 8];
            ulonglong2 b1 = *(const ulonglong2*)&Bs[kk][tn * 8 + 4];
            float av[8] = {a0.x, a0.y, a0.z, a0.w, a1.x, a1.y, a1.z, a1.w};
            unsigned long long bv[4] = {b0.x, b0.y, b1.x, b1.y};
#pragma unroll
            for (int i = 0; i < 8; i++) {
                unsigned long long aa = pack2(av[i], av[i]);
#pragma unroll
                for (int j = 0; j < 4; j++) acc[i][j] = ffma2(aa, bv[j], acc[i][j]);
            }
        }
        __syncthreads();
    }

    float bx[8];
#pragma unroll
    for (int c = 0; c < 8; c++) bx[c] = bias[n0 + tn * 8 + c];

#pragma unroll
    for (int i = 0; i < 8; i++) {
        float* cp = C + (size_t)(m0 + tm * 8 + i) * N + n0 + tn * 8;
        float2 v0 = unpack2(acc[i][0]);
        float2 v1 = unpack2(acc[i][1]);
        float2 v2 = unpack2(acc[i][2]);
        float2 v3 = unpack2(acc[i][3]);
        float4 o0 = make_float4(v0.x + bx[0], v0.y + bx[1], v1.x + bx[2], v1.y + bx[3]);
        float4 o1 = make_float4(v2.x + bx[4], v2.y + bx[5], v3.x + bx[6], v3.y + bx[7]);
        *(float4*)cp = o0;
        *(float4*)(cp + 4) = o1;
    }
}

// ---------------------------------------------------------------------------
// Grid barrier: monotonic counter, release fence before arrive, acquire
// fence after observe.
// ---------------------------------------------------------------------------
__device__ __forceinline__ void grid_bar(unsigned* epoch, int tid) {
    __threadfence();
    __syncthreads();
    *epoch += 1;
    if (tid == 0) {
        atomicAdd(&g_bar_count, 1u);
        const unsigned tgt = (*epoch) * (unsigned)RNCTA;
        while (*(volatile unsigned*)&g_bar_count < tgt) {}
        __threadfence();
    }
    __syncthreads();
}

// ---------------------------------------------------------------------------
// Recurrence v5. 128 CTAs x 512 threads, persistent.
// CTA cid: cols n0 = cid*8, all 64 batch rows.
// Smem: Wq[512 kp][4 g] float4 = {W[2kp][2g],W[2kp+1][2g],W[2kp][2g+1],
//       W[2kp+1][2g+1]} (32KB, loaded once); Hb0/Hb1[64][HST] staging;
//       Red[16 ks][16 slot][32 lb] (32KB) for the k-reduction.
// Thread tid = lb + 32*ks: b rows {lb, lb+32}, k sub-slice ks*8..ks*8+7 of
// each 128-chunk, all 8 cols. acc[i][j] = f32x2 over (even k, odd k).
// ---------------------------------------------------------------------------
__global__ __launch_bounds__(512) void rnn_recurrence(
    const float* __restrict__ W_hh, float* __restrict__ states)
{
    extern __shared__ float sm[];
    float* Wq  = sm;                        // 8192 floats (32KB)
    float* Hb0 = sm + 8192;                 // 64*132 = 8448
    float* Hb1 = Hb0 + RB * HST;            // 8448
    float* Red = Hb1 + RB * HST;            // 16*512 = 8192 (32KB)

    const int tid = threadIdx.x;
    const int n0 = blockIdx.x * 8;
    const int lb = tid & 31;
    const int ks = tid >> 5;                // warp id 0..15 (k sub-slice)

    // One-time: build pair-interleaved W slice (512 kp x 4 g float4s)
    for (int idx = tid; idx < 2048; idx += 512) {
        int kp = idx >> 2, g = idx & 3;
        const float* w0 = W_hh + (size_t)(2 * kp) * RH + n0 + 2 * g;
        const float* w1 = w0 + RH;
        float4 v;
        v.x = w0[0]; v.y = w1[0]; v.z = w0[1]; v.w = w1[1];
        *(float4*)(Wq + (size_t)idx * 4) = v;
    }
    __syncthreads();

    unsigned epoch = 0;

    // t = 0: h_0 = tanh(xp). 64 b x 8 cols = 512 outputs, 1 per thread.
    {
        float* op = states + (size_t)(tid >> 3) * RH + n0 + (tid & 7);
        *op = tanhf(*op);
    }
    grid_bar(&epoch, tid);

    // staging map: float4 index idx = q*512 + tid -> row idx>>5, col4 idx&31
    const int srow[4] = { (0 * 512 + tid) >> 5, (1 * 512 + tid) >> 5,
                          (2 * 512 + tid) >> 5, (3 * 512 + tid) >> 5 };
    const int scol = tid & 31;

    for (int t = 1; t < RT; ++t) {
        const float* hprev = states + (size_t)(t - 1) * (RB * RH);

        // prologue: stage chunk 0 (coalesced, L2-cached)
        float4 stage[4];
#pragma unroll
        for (int q = 0; q < 4; q++)
            stage[q] = ldcg4(hprev + (size_t)srow[q] * RH + scol * 4);

        unsigned long long a[2][8];
#pragma unroll
        for (int i = 0; i < 2; i++)
#pragma unroll
            for (int j = 0; j < 8; j++) a[i][j] = 0ull;

        for (int c = 0; c < NCHUNK; ++c) {
            float* buf = (c & 1) ? Hb1 : Hb0;

            // commit staged chunk c (lanes -> consecutive col4: conflict-free)
#pragma unroll
            for (int q = 0; q < 4; q++)
                *(float4*)(buf + srow[q] * HST + scol * 4) = stage[q];
            __syncthreads();

            // prefetch chunk c+1
            if (c + 1 < NCHUNK) {
                const float* gs = hprev + (c + 1) * CHUNK;
#pragma unroll
                for (int q = 0; q < 4; q++)
                    stage[q] = ldcg4(gs + (size_t)srow[q] * RH + scol * 4);
            }

            // compute: this warp's 8 k values x 2 b rows x 8 cols
            const float* hp0 = buf + lb * HST + ks * 8;
            const float* hp1 = buf + (lb + 32) * HST + ks * 8;
            ulonglong2 h0a = *(const ulonglong2*)(hp0);
            ulonglong2 h0b = *(const ulonglong2*)(hp0 + 4);
            ulonglong2 h1a = *(const ulonglong2*)(hp1);
            ulonglong2 h1b = *(const ulonglong2*)(hp1 + 4);
            unsigned long long hp0v[4] = { h0a.x, h0a.y, h0b.x, h0b.y };
            unsigned long long hp1v[4] = { h1a.x, h1a.y, h1b.x, h1b.y };

            const float* wp = Wq + (size_t)(c * 64 + ks * 4) * 16;  // kp*16 floats
#pragma unroll
            for (int p = 0; p < 4; p++) {
                ulonglong2 u0 = *(const ulonglong2*)(wp + p * 16);
                ulonglong2 u1 = *(const ulonglong2*)(wp + p * 16 + 4);
                ulonglong2 u2 = *(const ulonglong2*)(wp + p * 16 + 8);
                ulonglong2 u3 = *(const ulonglong2*)(wp + p * 16 + 12);
                unsigned long long h0 = hp0v[p], h1 = hp1v[p];
                a[0][0] = ffma2(h0, u0.x, a[0][0]);
                a[0][1] = ffma2(h0, u0.y, a[0][1]);
                a[0][2] = ffma2(h0, u1.x, a[0][2]);
                a[0][3] = ffma2(h0, u1.y, a[0][3]);
                a[0][4] = ffma2(h0, u2.x, a[0][4]);
                a[0][5] = ffma2(h0, u2.y, a[0][5]);
                a[0][6] = ffma2(h0, u3.x, a[0][6]);
                a[0][7] = ffma2(h0, u3.y, a[0][7]);
                a[1][0] = ffma2(h1, u0.x, a[1][0]);
                a[1][1] = ffma2(h1, u0.y, a[1][1]);
                a[1][2] = ffma2(h1, u1.x, a[1][2]);
                a[1][3] = ffma2(h1, u1.y, a[1][3]);
                a[1][4] = ffma2(h1, u2.x, a[1][4]);
                a[1][5] = ffma2(h1, u2.y, a[1][5]);
                a[1][6] = ffma2(h1, u3.x, a[1][6]);
                a[1][7] = ffma2(h1, u3.y, a[1][7]);
            }
            // no trailing sync: next iter writes the other buffer; reuse of
            // this buffer (c+2) is ordered by the sync at iteration c+1.
        }

        // publish partials: Red[ks][slot][lb], slot = i*8+j (lane-consecutive)
#pragma unroll
        for (int i = 0; i < 2; i++)
#pragma unroll
            for (int j = 0; j < 8; j++) {
                float2 f = unpack2(a[i][j]);
                Red[ks * 512 + (i * 8 + j) * 32 + lb] = f.x + f.y;
            }
        __syncthreads();

        // 16-way k-reduction + tanh epilogue: 512 threads, 1 output each
        {
            const int lb2 = tid & 31;
            const int jj = (tid >> 5) & 7;
            const int ii = tid >> 8;
            const int slot = ii * 8 + jj;
            float s = 0.0f;
#pragma unroll
            for (int q = 0; q < 16; q++)
                s += Red[q * 512 + slot * 32 + lb2];
            const int b = lb2 + 32 * ii;
            float* op = states + (size_t)t * (RB * RH) + (size_t)b * RH + n0 + jj;
            float xp = *op;
            *op = tanhf(xp + s);
        }

        grid_bar(&epoch, tid);
    }
}

// ---------------------------------------------------------------------------
extern "C" void kernel_launch(void* const* d_in, const int* in_sizes, int n_in,
                              void* d_out, int out_size)
{
    const float* X    = (const float*)d_in[0];
    const float* W_xh = (const float*)d_in[1];
    const float* W_hh = (const float*)d_in[2];
    const float* b_h  = (const float*)d_in[3];
    const float* W_hq = (const float*)d_in[4];
    const float* b_q  = (const float*)d_in[5];

    float* outputs = (float*)d_out;                      // [T*B, O]
    float* states  = outputs + (size_t)RT * RB * RO;     // [T*B, H]

    const int M = RT * RB;  // 32768
    const int rec_smem =
        (8192 + 2 * RB * HST + 16 * 512) * (int)sizeof(float);  // ~133 KB

    cudaFuncSetAttribute(rnn_recurrence,
                         cudaFuncAttributeMaxDynamicSharedMemorySize, rec_smem);

    dim3 blk(256);
    dim3 g1(RH / GBN, M / GBM);   // Xproj: N=1024, K=512 (resets barrier ctr)
    sgemm_bias<<<g1, blk>>>(X, W_xh, b_h, states, M, RH, RI, 1);

    rnn_recurrence<<<RNCTA, 512, rec_smem>>>(W_hh, states);

    dim3 g3(RO / GBN, M / GBM);   // outputs: N=512, K=1024
    sgemm_bias<<<g3, blk>>>(states, W_hq, b_q, outputs, M, RO, RH, 0);
}

// round 7
// speedup vs baseline: 1.4138x; 1.0467x over previous
#include <cuda_runtime.h>
#include <cuda_bf16.h>

// ---------------------------------------------------------------------------
// RNN: h_t = tanh(X_t @ W_xh + b_h + h_{t-1} @ W_hh) ; y_t = h_t @ W_hq + b_q
// out = [outputs (T*B*O floats) | states (T*B*H floats)]
// T=512 B=64 I=512 H=1024 O=512
//
// R6: (a) recurrence reads/writes a transposed pair-packed __device__ scratch
// hT[2][k][b-pair] -> coalesced LDG.64 = ready f32x2, no smem staging, no
// chunk syncs; .cg both ways (L1 staleness across 2-step buffer reuse).
// (b) GEMM column remap {tn*4, tn*4+64} kills the 4-way Bs bank conflicts.
// ---------------------------------------------------------------------------

#define RT 512
#define RB 64
#define RH 1024
#define RI 512
#define RO 512
#define RNCTA 128

__device__ unsigned g_bar_count;
// transposed hidden-state scratch: [ping-pong][k][b-pair(lo=b, hi=b+32)]
__device__ __align__(16) float2 g_hT[2][RH][RB / 2];

// ---- f32x2 packed math helpers ----
__device__ __forceinline__ unsigned long long ffma2(unsigned long long a,
                                                    unsigned long long b,
                                                    unsigned long long c) {
    unsigned long long d;
    asm("fma.rn.f32x2 %0, %1, %2, %3;" : "=l"(d) : "l"(a), "l"(b), "l"(c));
    return d;
}
__device__ __forceinline__ unsigned long long pack2(float lo, float hi) {
    unsigned long long r;
    asm("mov.b64 %0, {%1, %2};" : "=l"(r) : "f"(lo), "f"(hi));
    return r;
}
__device__ __forceinline__ float2 unpack2(unsigned long long v) {
    float lo, hi;
    asm("mov.b64 {%0, %1}, %2;" : "=f"(lo), "=f"(hi) : "l"(v));
    return make_float2(lo, hi);
}
__device__ __forceinline__ unsigned long long ldcg64(const void* p) {
    unsigned long long v;
    asm volatile("ld.global.cg.b64 %0, [%1];" : "=l"(v) : "l"(p));
    return v;
}
__device__ __forceinline__ void stcg32(float* p, float v) {
    asm volatile("st.global.cg.f32 [%0], %1;" :: "l"(p), "f"(v));
}

// ---------------------------------------------------------------------------
// fp32 GEMM + bias. R6: thread columns = {tn*4 .. +3} U {tn*4+64 .. +67}
// -> Bs reads are 16B-lane-stride (conflict-free, 2 wf per LDS.128).
// ---------------------------------------------------------------------------
#define GBM 128
#define GBN 128
#define GBK 16

__global__ __launch_bounds__(256) void sgemm_bias(
    const float* __restrict__ A, const float* __restrict__ B,
    const float* __restrict__ bias, float* __restrict__ C,
    int M, int N, int K, int reset_bar)
{
    if (reset_bar && blockIdx.x == 0 && blockIdx.y == 0 && threadIdx.x == 0)
        g_bar_count = 0u;

    __shared__ __align__(16) float As[GBK][GBM + 4];
    __shared__ __align__(16) float Bs[GBK][GBN];

    const int tid = threadIdx.x;
    const int m0 = blockIdx.y * GBM;
    const int n0 = blockIdx.x * GBN;
    const int tm = tid >> 4;
    const int tn = tid & 15;

    unsigned long long acc[8][4];
#pragma unroll
    for (int i = 0; i < 8; i++)
#pragma unroll
        for (int j = 0; j < 4; j++) acc[i][j] = 0ull;

    const int arow = tid >> 2;
    const int acol4 = tid & 3;
    const int brow = tid >> 5;
    const int bcol4 = tid & 31;

    for (int k0 = 0; k0 < K; k0 += GBK) {
#pragma unroll
        for (int p = 0; p < 2; p++) {
            int r = arow + p * 64;
            float4 v = *(const float4*)(A + (size_t)(m0 + r) * K + k0 + acol4 * 4);
            As[acol4 * 4 + 0][r] = v.x;
            As[acol4 * 4 + 1][r] = v.y;
            As[acol4 * 4 + 2][r] = v.z;
            As[acol4 * 4 + 3][r] = v.w;
        }
#pragma unroll
        for (int p = 0; p < 2; p++) {
            int r = brow + p * 8;
            float4 v = *(const float4*)(B + (size_t)(k0 + r) * N + n0 + bcol4 * 4);
            *(float4*)&Bs[r][bcol4 * 4] = v;
        }
        __syncthreads();

#pragma unroll
        for (int kk = 0; kk < GBK; kk++) {
            float4 a0 = *(const float4*)&As[kk][tm * 8];
            float4 a1 = *(const float4*)&As[kk][tm * 8 + 4];
            ulonglong2 b0 = *(const ulonglong2*)&Bs[kk][tn * 4];        // cols tn*4..+3
            ulonglong2 b1 = *(const ulonglong2*)&Bs[kk][tn * 4 + 64];   // cols +64..+67
            float av[8] = {a0.x, a0.y, a0.z, a0.w, a1.x, a1.y, a1.z, a1.w};
            unsigned long long bv[4] = {b0.x, b0.y, b1.x, b1.y};
#pragma unroll
            for (int i = 0; i < 8; i++) {
                unsigned long long aa = pack2(av[i], av[i]);
#pragma unroll
                for (int j = 0; j < 4; j++) acc[i][j] = ffma2(aa, bv[j], acc[i][j]);
            }
        }
        __syncthreads();
    }

    float bx[8];
#pragma unroll
    for (int c = 0; c < 4; c++) {
        bx[c]     = bias[n0 + tn * 4 + c];
        bx[4 + c] = bias[n0 + tn * 4 + 64 + c];
    }

#pragma unroll
    for (int i = 0; i < 8; i++) {
        float* cp0 = C + (size_t)(m0 + tm * 8 + i) * N + n0 + tn * 4;
        float2 v0 = unpack2(acc[i][0]);
        float2 v1 = unpack2(acc[i][1]);
        float2 v2 = unpack2(acc[i][2]);
        float2 v3 = unpack2(acc[i][3]);
        float4 o0 = make_float4(v0.x + bx[0], v0.y + bx[1], v1.x + bx[2], v1.y + bx[3]);
        float4 o1 = make_float4(v2.x + bx[4], v2.y + bx[5], v3.x + bx[6], v3.y + bx[7]);
        *(float4*)cp0 = o0;
        *(float4*)(cp0 + 64) = o1;
    }
}

// ---------------------------------------------------------------------------
// Grid barrier (monotonic counter; release fence before arrive, acquire after)
// ---------------------------------------------------------------------------
__device__ __forceinline__ void grid_bar(unsigned* epoch, int tid) {
    __threadfence();
    __syncthreads();
    *epoch += 1;
    if (tid == 0) {
        atomicAdd(&g_bar_count, 1u);
        const unsigned tgt = (*epoch) * (unsigned)RNCTA;
        while (*(volatile unsigned*)&g_bar_count < tgt) {}
        __threadfence();
    }
    __syncthreads();
}

// ---------------------------------------------------------------------------
// Recurrence v6. 128 CTAs x 512 threads, persistent. CTA = 8 cols (n0=cid*8),
// all 64 b. Thread tid = lb + 32*ks: warp ks owns k-slice [64ks, 64ks+64),
// lane lb owns b-pair (lb, lb+32), all 8 cols.
// Per k: 1 LDG.64 from g_hT (coalesced, = f32x2 pair) + 4 broadcast LDS.128
// of duplicated W pairs + 8 FFMA2. No staging, no chunk syncs.
// Smem: Wd[1024][8] u64 dup-pairs (64KB, once), Red[16][8][32] f32x2 (32KB).
// ---------------------------------------------------------------------------
__global__ __launch_bounds__(512) void rnn_recurrence(
    const float* __restrict__ W_hh, float* __restrict__ states)
{
    extern __shared__ __align__(16) unsigned long long smu[];
    unsigned long long* Wd = smu;                       // [1024][8]  64KB
    float* Red = (float*)(smu + RH * 8);                // [16][8][32] f32x2 32KB

    const int tid = threadIdx.x;
    const int n0 = blockIdx.x * 8;
    const int lb = tid & 31;
    const int ks = tid >> 5;     // warp id 0..15 = k slice

    // One-time: duplicated W pairs Wd[k][j] = (W[k][n0+j], same)
    for (int idx = tid; idx < RH * 8; idx += 512) {
        int k = idx >> 3, j = idx & 7;
        float w = W_hh[(size_t)k * RH + n0 + j];
        Wd[idx] = pack2(w, w);
    }
    __syncthreads();

    unsigned epoch = 0;

    // t = 0: h_0 = tanh(xp); write states and hT[0]
    {
        int b = tid >> 3, j = tid & 7;
        float* op = states + (size_t)b * RH + n0 + j;
        float v = tanhf(*op);
        *op = v;
        stcg32((float*)&g_hT[0][n0 + j][b & 31] + (b >> 5), v);
    }
    grid_bar(&epoch, tid);

    for (int t = 1; t < RT; ++t) {
        const float2* hsrc = g_hT[(t - 1) & 1][0];   // flat [RH*32] float2

        unsigned long long a[8];
#pragma unroll
        for (int j = 0; j < 8; j++) a[j] = 0ull;

        const float2* hp = hsrc + (size_t)(ks * 64) * 32 + lb;
        const unsigned long long* wp = Wd + (size_t)(ks * 64) * 8;

#pragma unroll 4
        for (int i = 0; i < 64; i++) {
            unsigned long long h = ldcg64(hp + (size_t)i * 32);
            ulonglong2 w01 = *(const ulonglong2*)(wp + i * 8);
            ulonglong2 w23 = *(const ulonglong2*)(wp + i * 8 + 2);
            ulonglong2 w45 = *(const ulonglong2*)(wp + i * 8 + 4);
            ulonglong2 w67 = *(const ulonglong2*)(wp + i * 8 + 6);
            a[0] = ffma2(h, w01.x, a[0]);
            a[1] = ffma2(h, w01.y, a[1]);
            a[2] = ffma2(h, w23.x, a[2]);
            a[3] = ffma2(h, w23.y, a[3]);
            a[4] = ffma2(h, w45.x, a[4]);
            a[5] = ffma2(h, w45.y, a[5]);
            a[6] = ffma2(h, w67.x, a[6]);
            a[7] = ffma2(h, w67.y, a[7]);
        }

        // publish partials: Red[ks][j][lb] (float2 = b-pair), STS.64 contiguous
#pragma unroll
        for (int j = 0; j < 8; j++)
            *(unsigned long long*)(Red + (((size_t)ks * 8 + j) * 32 + lb) * 2) = a[j];
        __syncthreads();

        // 16-way k-reduce + tanh: thread (lb2, jj, ii) -> b = lb2 + 32*ii
        {
            const int lb2 = tid & 31;
            const int jj = (tid >> 5) & 7;
            const int ii = tid >> 8;
            const float* rp = Red + ((size_t)jj * 32 + lb2) * 2 + ii;
            float s = 0.0f;
#pragma unroll
            for (int q = 0; q < 16; q++)
                s += rp[(size_t)q * 512];     // q*8*32*2 floats
            const int b = lb2 + 32 * ii;
            float* op = states + (size_t)t * (RB * RH) + (size_t)b * RH + n0 + jj;
            float v = tanhf(*op + s);
            *op = v;
            stcg32((float*)&g_hT[t & 1][n0 + jj][lb2] + ii, v);
        }

        grid_bar(&epoch, tid);
    }
}

// ---------------------------------------------------------------------------
extern "C" void kernel_launch(void* const* d_in, const int* in_sizes, int n_in,
                              void* d_out, int out_size)
{
    const float* X    = (const float*)d_in[0];
    const float* W_xh = (const float*)d_in[1];
    const float* W_hh = (const float*)d_in[2];
    const float* b_h  = (const float*)d_in[3];
    const float* W_hq = (const float*)d_in[4];
    const float* b_q  = (const float*)d_in[5];

    float* outputs = (float*)d_out;                      // [T*B, O]
    float* states  = outputs + (size_t)RT * RB * RO;     // [T*B, H]

    const int M = RT * RB;  // 32768
    const int rec_smem = RH * 8 * 8 + 16 * 8 * 32 * 8;   // 64KB + 32KB

    cudaFuncSetAttribute(rnn_recurrence,
                         cudaFuncAttributeMaxDynamicSharedMemorySize, rec_smem);

    dim3 blk(256);
    dim3 g1(RH / GBN, M / GBM);   // Xproj: N=1024, K=512 (resets barrier ctr)
    sgemm_bias<<<g1, blk>>>(X, W_xh, b_h, states, M, RH, RI, 1);

    rnn_recurrence<<<RNCTA, 512, rec_smem>>>(W_hh, states);

    dim3 g3(RO / GBN, M / GBM);   // outputs: N=512, K=1024
    sgemm_bias<<<g3, blk>>>(states, W_hq, b_q, outputs, M, RO, RH, 0);
}

// round 8
// speedup vs baseline: 1.5322x; 1.0837x over previous
#include <cuda_runtime.h>
#include <cuda_bf16.h>

// ---------------------------------------------------------------------------
// RNN: h_t = tanh(X_t @ W_xh + b_h + h_{t-1} @ W_hh) ; y_t = h_t @ W_hq + b_q
// out = [outputs (T*B*O floats) | states (T*B*H floats)]
// T=512 B=64 I=512 H=1024 O=512
//
// R7: (a) recurrence CTA = 16 cols x 32-batch half -> h L2 traffic halved
// (16 MB/step); (b) grid barrier split into two independent 64-CTA groups
// (batch halves are independent in the recurrence); (c) GEMM A-operands
// pre-duplicated as u64 pairs in smem (no per-kk pack MOVs).
// ---------------------------------------------------------------------------

#define RT 512
#define RB 64
#define RH 1024
#define RI 512
#define RO 512

__device__ unsigned g_bar2[2];
// transposed hidden scratch: [ping-pong][k][pair p = (b=2p, b=2p+1)]
__device__ __align__(16) float2 g_hT[2][RH][RB / 2];

// ---- f32x2 packed math helpers ----
__device__ __forceinline__ unsigned long long ffma2(unsigned long long a,
                                                    unsigned long long b,
                                                    unsigned long long c) {
    unsigned long long d;
    asm("fma.rn.f32x2 %0, %1, %2, %3;" : "=l"(d) : "l"(a), "l"(b), "l"(c));
    return d;
}
__device__ __forceinline__ unsigned long long add2(unsigned long long a,
                                                   unsigned long long b) {
    unsigned long long d;
    asm("add.rn.f32x2 %0, %1, %2;" : "=l"(d) : "l"(a), "l"(b));
    return d;
}
__device__ __forceinline__ unsigned long long pack2(float lo, float hi) {
    unsigned long long r;
    asm("mov.b64 %0, {%1, %2};" : "=l"(r) : "f"(lo), "f"(hi));
    return r;
}
__device__ __forceinline__ float2 unpack2(unsigned long long v) {
    float lo, hi;
    asm("mov.b64 {%0, %1}, %2;" : "=f"(lo), "=f"(hi) : "l"(v));
    return make_float2(lo, hi);
}
__device__ __forceinline__ unsigned long long ldcg64(const void* p) {
    unsigned long long v;
    asm volatile("ld.global.cg.b64 %0, [%1];" : "=l"(v) : "l"(p));
    return v;
}
__device__ __forceinline__ void stcg32(float* p, float v) {
    asm volatile("st.global.cg.f32 [%0], %1;" :: "l"(p), "f"(v));
}
__device__ __forceinline__ void stcg64(void* p, unsigned long long v) {
    asm volatile("st.global.cg.b64 [%0], %1;" :: "l"(p), "l"(v));
}

// ---------------------------------------------------------------------------
// fp32 GEMM + bias. R7: A stored in smem as duplicated u64 pairs (Asd) ->
// inner loop has zero pack MOVs. Columns {tn*4, tn*4+64} (conflict-free Bs).
// ---------------------------------------------------------------------------
#define GBM 128
#define GBN 128
#define GBK 16
#define ASTR (GBM + 2)   // Asd row stride in u64 (pad: rotates banks per row)

__global__ __launch_bounds__(256) void sgemm_bias(
    const float* __restrict__ A, const float* __restrict__ B,
    const float* __restrict__ bias, float* __restrict__ C,
    int M, int N, int K, int reset_bar)
{
    if (reset_bar && blockIdx.x == 0 && blockIdx.y == 0 && threadIdx.x == 0) {
        g_bar2[0] = 0u;
        g_bar2[1] = 0u;
    }

    __shared__ __align__(16) unsigned long long Asd[GBK * ASTR];  // dup pairs
    __shared__ __align__(16) float Bs[GBK][GBN];

    const int tid = threadIdx.x;
    const int m0 = blockIdx.y * GBM;
    const int n0 = blockIdx.x * GBN;
    const int tm = tid >> 4;
    const int tn = tid & 15;

    unsigned long long acc[8][4];
#pragma unroll
    for (int i = 0; i < 8; i++)
#pragma unroll
        for (int j = 0; j < 4; j++) acc[i][j] = 0ull;

    const int arow = tid >> 2;
    const int acol4 = tid & 3;
    const int brow = tid >> 5;
    const int bcol4 = tid & 31;

    for (int k0 = 0; k0 < K; k0 += GBK) {
#pragma unroll
        for (int p = 0; p < 2; p++) {
            int r = arow + p * 64;
            float4 v = *(const float4*)(A + (size_t)(m0 + r) * K + k0 + acol4 * 4);
            Asd[(acol4 * 4 + 0) * ASTR + r] = pack2(v.x, v.x);
            Asd[(acol4 * 4 + 1) * ASTR + r] = pack2(v.y, v.y);
            Asd[(acol4 * 4 + 2) * ASTR + r] = pack2(v.z, v.z);
            Asd[(acol4 * 4 + 3) * ASTR + r] = pack2(v.w, v.w);
        }
#pragma unroll
        for (int p = 0; p < 2; p++) {
            int r = brow + p * 8;
            float4 v = *(const float4*)(B + (size_t)(k0 + r) * N + n0 + bcol4 * 4);
            *(float4*)&Bs[r][bcol4 * 4] = v;
        }
        __syncthreads();

#pragma unroll
        for (int kk = 0; kk < GBK; kk++) {
            const unsigned long long* ar = Asd + kk * ASTR + tm * 8;
            ulonglong2 a01 = *(const ulonglong2*)(ar + 0);
            ulonglong2 a23 = *(const ulonglong2*)(ar + 2);
            ulonglong2 a45 = *(const ulonglong2*)(ar + 4);
            ulonglong2 a67 = *(const ulonglong2*)(ar + 6);
            ulonglong2 b0 = *(const ulonglong2*)&Bs[kk][tn * 4];
            ulonglong2 b1 = *(const ulonglong2*)&Bs[kk][tn * 4 + 64];
            unsigned long long av[8] = {a01.x, a01.y, a23.x, a23.y,
                                        a45.x, a45.y, a67.x, a67.y};
            unsigned long long bv[4] = {b0.x, b0.y, b1.x, b1.y};
#pragma unroll
            for (int i = 0; i < 8; i++)
#pragma unroll
                for (int j = 0; j < 4; j++)
                    acc[i][j] = ffma2(av[i], bv[j], acc[i][j]);
        }
        __syncthreads();
    }

    float bx[8];
#pragma unroll
    for (int c = 0; c < 4; c++) {
        bx[c]     = bias[n0 + tn * 4 + c];
        bx[4 + c] = bias[n0 + tn * 4 + 64 + c];
    }

#pragma unroll
    for (int i = 0; i < 8; i++) {
        float* cp0 = C + (size_t)(m0 + tm * 8 + i) * N + n0 + tn * 4;
        float2 v0 = unpack2(acc[i][0]);
        float2 v1 = unpack2(acc[i][1]);
        float2 v2 = unpack2(acc[i][2]);
        float2 v3 = unpack2(acc[i][3]);
        float4 o0 = make_float4(v0.x + bx[0], v0.y + bx[1], v1.x + bx[2], v1.y + bx[3]);
        float4 o1 = make_float4(v2.x + bx[4], v2.y + bx[5], v3.x + bx[6], v3.y + bx[7]);
        *(float4*)cp0 = o0;
        *(float4*)(cp0 + 64) = o1;
    }
}

// ---------------------------------------------------------------------------
// Group grid barrier: 64 CTAs per batch-half group, monotonic counter.
// ---------------------------------------------------------------------------
__device__ __forceinline__ void grid_bar_g(unsigned* epoch, int tid, int grp) {
    __threadfence();
    __syncthreads();
    *epoch += 1;
    if (tid == 0) {
        atomicAdd(&g_bar2[grp], 1u);
        const unsigned tgt = (*epoch) * 64u;
        while (*(volatile unsigned*)&g_bar2[grp] < tgt) {}
        __threadfence();
    }
    __syncthreads();
}

// ---------------------------------------------------------------------------
// Recurrence v7. 128 CTAs x 512 threads, persistent.
// CTA cid: cols n0 = (cid&63)*16, batch half hb = cid>>6 (pairs hb*16..+15).
// Thread tid = lb + 32*ks: warp ks owns k-slice [64ks, 64ks+64);
// lane: p = lb&15 (batch pair), jh = lb>>4 (8-col half).
// Per k: 1 LDG.64 g_hT (dup across half-warps, 1 line) + 4 LDS.128 of dup W
// pairs (two 64B-apart bcast addrs: conflict-free) + 8 FFMA2.
// Smem: Wd[1024][16] u64 dup pairs (128KB, once), Red[8][16][32] u64 (32KB).
// ---------------------------------------------------------------------------
__global__ __launch_bounds__(512) void rnn_recurrence(
    const float* __restrict__ W_hh, float* __restrict__ states)
{
    extern __shared__ __align__(16) unsigned long long smu[];
    unsigned long long* Wd  = smu;            // [1024][16] u64   128 KB
    unsigned long long* Red = smu + RH * 16;  // [8][16][32] u64   32 KB

    const int tid = threadIdx.x;
    const int cid = blockIdx.x;
    const int n0 = (cid & 63) * 16;
    const int hb = cid >> 6;
    const int lb = tid & 31;
    const int ks = tid >> 5;
    const int p  = lb & 15;
    const int jh = lb >> 4;

    // One-time: duplicated W pairs Wd[k][j] = (W[k][n0+j], same), j = 0..15
    for (int idx = tid; idx < RH * 16; idx += 512) {
        int k = idx >> 4, j = idx & 15;
        float w = W_hh[(size_t)k * RH + n0 + j];
        Wd[idx] = pack2(w, w);
    }
    __syncthreads();

    unsigned epoch = 0;

    // t = 0: h_0 = tanh(xp). 32 b x 16 cols = 512 outputs, 1/thread.
    {
        int j = tid >> 5, b = hb * 32 + (tid & 31);
        float* op = states + (size_t)b * RH + n0 + j;
        float v = tanhf(*op);
        *op = v;
        stcg32((float*)&g_hT[0][n0 + j][0] + b, v);
    }
    grid_bar_g(&epoch, tid, hb);

    for (int t = 1; t < RT; ++t) {
        const float2* hsrc = &g_hT[(t - 1) & 1][0][hb * 16 + p];

        unsigned long long a[8];
#pragma unroll
        for (int c = 0; c < 8; c++) a[c] = 0ull;

        const unsigned long long* wp = Wd + (size_t)(ks * 64) * 16 + jh * 8;
        const float2* hp = hsrc + (size_t)(ks * 64) * 32;

#pragma unroll 8
        for (int i = 0; i < 64; i++) {
            unsigned long long h = ldcg64(hp + (size_t)i * 32);
            ulonglong2 w01 = *(const ulonglong2*)(wp + i * 16);
            ulonglong2 w23 = *(const ulonglong2*)(wp + i * 16 + 2);
            ulonglong2 w45 = *(const ulonglong2*)(wp + i * 16 + 4);
            ulonglong2 w67 = *(const ulonglong2*)(wp + i * 16 + 6);
            a[0] = ffma2(h, w01.x, a[0]);
            a[1] = ffma2(h, w01.y, a[1]);
            a[2] = ffma2(h, w23.x, a[2]);
            a[3] = ffma2(h, w23.y, a[3]);
            a[4] = ffma2(h, w45.x, a[4]);
            a[5] = ffma2(h, w45.y, a[5]);
            a[6] = ffma2(h, w67.x, a[6]);
            a[7] = ffma2(h, w67.y, a[7]);
        }

        // publish partials: Red[c][ks][lb] (STS.64, lane-contiguous)
#pragma unroll
        for (int c = 0; c < 8; c++)
            Red[(size_t)c * 512 + ks * 32 + lb] = a[c];
        __syncthreads();

        // k-reduce (16-way) + tanh epilogue: 256 threads, 1 pair-output each
        if (tid < 256) {
            const int rp = tid & 15;          // batch pair within half
            const int rj = tid >> 4;          // col 0..15
            const int rc = rj & 7;
            const int rh2 = rj >> 3;
            const unsigned long long* rsrc =
                Red + (size_t)rc * 512 + rh2 * 16 + rp;
            unsigned long long s = rsrc[0];
#pragma unroll
            for (int q = 1; q < 16; q++) s = add2(s, rsrc[(size_t)q * 32]);
            float2 f = unpack2(s);

            const int P = hb * 16 + rp;       // global pair -> batches 2P, 2P+1
            float* op0 = states + (size_t)t * (RB * RH) + (size_t)(2 * P) * RH + n0 + rj;
            float* op1 = op0 + RH;
            float v0 = tanhf(*op0 + f.x);
            float v1 = tanhf(*op1 + f.y);
            *op0 = v0;
            *op1 = v1;
            stcg64(&g_hT[t & 1][n0 + rj][P], pack2(v0, v1));
        }

        if (t < RT - 1) grid_bar_g(&epoch, tid, hb);
    }
}

// ---------------------------------------------------------------------------
extern "C" void kernel_launch(void* const* d_in, const int* in_sizes, int n_in,
                              void* d_out, int out_size)
{
    const float* X    = (const float*)d_in[0];
    const float* W_xh = (const float*)d_in[1];
    const float* W_hh = (const float*)d_in[2];
    const float* b_h  = (const float*)d_in[3];
    const float* W_hq = (const float*)d_in[4];
    const float* b_q  = (const float*)d_in[5];

    float* outputs = (float*)d_out;                      // [T*B, O]
    float* states  = outputs + (size_t)RT * RB * RO;     // [T*B, H]

    const int M = RT * RB;  // 32768
    const int rec_smem = (RH * 16 + 8 * 16 * 32) * 8;    // 128KB + 32KB

    cudaFuncSetAttribute(rnn_recurrence,
                         cudaFuncAttributeMaxDynamicSharedMemorySize, rec_smem);

    dim3 blk(256);
    dim3 g1(RH / GBN, M / GBM);   // Xproj: N=1024, K=512 (resets barrier ctrs)
    sgemm_bias<<<g1, blk>>>(X, W_xh, b_h, states, M, RH, RI, 1);

    rnn_recurrence<<<128, 512, rec_smem>>>(W_hh, states);

    dim3 g3(RO / GBN, M / GBM);   // outputs: N=512, K=1024
    sgemm_bias<<<g3, blk>>>(states, W_hq, b_q, outputs, M, RO, RH, 0);
}

// round 9
// speedup vs baseline: 1.6865x; 1.1007x over previous
#include <cuda_runtime.h>
#include <cuda_bf16.h>

// ---------------------------------------------------------------------------
// RNN: h_t = tanh(X_t @ W_xh + b_h + h_{t-1} @ W_hh) ; y_t = h_t @ W_hq + b_q
// out = [outputs (T*B*O floats) | states (T*B*H floats)]
// T=512 B=64 I=512 H=1024 O=512
//
// R8: GEMM reverted to R6 (A-dup regressed). Recurrence: software-pipelined
// h LDGs (register double-buffer, hides L2 latency), release/acquire barrier
// (drops full MEMBARs). Layout unchanged from R7 (16 cols x 32-b half,
// split 64-CTA barrier groups, g_hT transposed pair scratch).
// ---------------------------------------------------------------------------

#define RT 512
#define RB 64
#define RH 1024
#define RI 512
#define RO 512

__device__ unsigned g_bar2[2];
// transposed hidden scratch: [ping-pong][k][pair p = (b=2p, b=2p+1)]
__device__ __align__(16) float2 g_hT[2][RH][RB / 2];

// ---- f32x2 packed math helpers ----
__device__ __forceinline__ unsigned long long ffma2(unsigned long long a,
                                                    unsigned long long b,
                                                    unsigned long long c) {
    unsigned long long d;
    asm("fma.rn.f32x2 %0, %1, %2, %3;" : "=l"(d) : "l"(a), "l"(b), "l"(c));
    return d;
}
__device__ __forceinline__ unsigned long long add2(unsigned long long a,
                                                   unsigned long long b) {
    unsigned long long d;
    asm("add.rn.f32x2 %0, %1, %2;" : "=l"(d) : "l"(a), "l"(b));
    return d;
}
__device__ __forceinline__ unsigned long long pack2(float lo, float hi) {
    unsigned long long r;
    asm("mov.b64 %0, {%1, %2};" : "=l"(r) : "f"(lo), "f"(hi));
    return r;
}
__device__ __forceinline__ float2 unpack2(unsigned long long v) {
    float lo, hi;
    asm("mov.b64 {%0, %1}, %2;" : "=f"(lo), "=f"(hi) : "l"(v));
    return make_float2(lo, hi);
}
__device__ __forceinline__ unsigned long long ldcg64(const void* p) {
    unsigned long long v;
    asm volatile("ld.global.cg.b64 %0, [%1];" : "=l"(v) : "l"(p));
    return v;
}
__device__ __forceinline__ void stcg32(float* p, float v) {
    asm volatile("st.global.cg.f32 [%0], %1;" :: "l"(p), "f"(v));
}
__device__ __forceinline__ void stcg64(void* p, unsigned long long v) {
    asm volatile("st.global.cg.b64 [%0], %1;" :: "l"(p), "l"(v));
}
__device__ __forceinline__ void red_release_add(unsigned* p, unsigned v) {
    asm volatile("red.release.gpu.global.add.u32 [%0], %1;" :: "l"(p), "r"(v)
                 : "memory");
}
__device__ __forceinline__ unsigned ld_acquire(const unsigned* p) {
    unsigned v;
    asm volatile("ld.acquire.gpu.global.u32 %0, [%1];" : "=r"(v) : "l"(p)
                 : "memory");
    return v;
}

// ---------------------------------------------------------------------------
// fp32 GEMM + bias — exact R6 version (best measured: 632us, fma 68.7%).
// Columns {tn*4, tn*4+64}: conflict-free Bs reads.
// ---------------------------------------------------------------------------
#define GBM 128
#define GBN 128
#define GBK 16

__global__ __launch_bounds__(256) void sgemm_bias(
    const float* __restrict__ A, const float* __restrict__ B,
    const float* __restrict__ bias, float* __restrict__ C,
    int M, int N, int K, int reset_bar)
{
    if (reset_bar && blockIdx.x == 0 && blockIdx.y == 0 && threadIdx.x == 0) {
        g_bar2[0] = 0u;
        g_bar2[1] = 0u;
    }

    __shared__ __align__(16) float As[GBK][GBM + 4];
    __shared__ __align__(16) float Bs[GBK][GBN];

    const int tid = threadIdx.x;
    const int m0 = blockIdx.y * GBM;
    const int n0 = blockIdx.x * GBN;
    const int tm = tid >> 4;
    const int tn = tid & 15;

    unsigned long long acc[8][4];
#pragma unroll
    for (int i = 0; i < 8; i++)
#pragma unroll
        for (int j = 0; j < 4; j++) acc[i][j] = 0ull;

    const int arow = tid >> 2;
    const int acol4 = tid & 3;
    const int brow = tid >> 5;
    const int bcol4 = tid & 31;

    for (int k0 = 0; k0 < K; k0 += GBK) {
#pragma unroll
        for (int p = 0; p < 2; p++) {
            int r = arow + p * 64;
            float4 v = *(const float4*)(A + (size_t)(m0 + r) * K + k0 + acol4 * 4);
            As[acol4 * 4 + 0][r] = v.x;
            As[acol4 * 4 + 1][r] = v.y;
            As[acol4 * 4 + 2][r] = v.z;
            As[acol4 * 4 + 3][r] = v.w;
        }
#pragma unroll
        for (int p = 0; p < 2; p++) {
            int r = brow + p * 8;
            float4 v = *(const float4*)(B + (size_t)(k0 + r) * N + n0 + bcol4 * 4);
            *(float4*)&Bs[r][bcol4 * 4] = v;
        }
        __syncthreads();

#pragma unroll
        for (int kk = 0; kk < GBK; kk++) {
            float4 a0 = *(const float4*)&As[kk][tm * 8];
            float4 a1 = *(const float4*)&As[kk][tm * 8 + 4];
            ulonglong2 b0 = *(const ulonglong2*)&Bs[kk][tn * 4];
            ulonglong2 b1 = *(const ulonglong2*)&Bs[kk][tn * 4 + 64];
            float av[8] = {a0.x, a0.y, a0.z, a0.w, a1.x, a1.y, a1.z, a1.w};
            unsigned long long bv[4] = {b0.x, b0.y, b1.x, b1.y};
#pragma unroll
            for (int i = 0; i < 8; i++) {
                unsigned long long aa = pack2(av[i], av[i]);
#pragma unroll
                for (int j = 0; j < 4; j++) acc[i][j] = ffma2(aa, bv[j], acc[i][j]);
            }
        }
        __syncthreads();
    }

    float bx[8];
#pragma unroll
    for (int c = 0; c < 4; c++) {
        bx[c]     = bias[n0 + tn * 4 + c];
        bx[4 + c] = bias[n0 + tn * 4 + 64 + c];
    }

#pragma unroll
    for (int i = 0; i < 8; i++) {
        float* cp0 = C + (size_t)(m0 + tm * 8 + i) * N + n0 + tn * 4;
        float2 v0 = unpack2(acc[i][0]);
        float2 v1 = unpack2(acc[i][1]);
        float2 v2 = unpack2(acc[i][2]);
        float2 v3 = unpack2(acc[i][3]);
        float4 o0 = make_float4(v0.x + bx[0], v0.y + bx[1], v1.x + bx[2], v1.y + bx[3]);
        float4 o1 = make_float4(v2.x + bx[4], v2.y + bx[5], v3.x + bx[6], v3.y + bx[7]);
        *(float4*)cp0 = o0;
        *(float4*)(cp0 + 64) = o1;
    }
}

// ---------------------------------------------------------------------------
// Group grid barrier: 64 CTAs per group. release-arrive / acquire-spin;
// __syncthreads provides CTA-scope ordering, fence cumulativity lifts it to
// gpu scope through the release atomic / acquire load.
// ---------------------------------------------------------------------------
__device__ __forceinline__ void grid_bar_g(unsigned* epoch, int tid, int grp) {
    __syncthreads();
    *epoch += 1;
    if (tid == 0) {
        red_release_add(&g_bar2[grp], 1u);
        const unsigned tgt = (*epoch) * 64u;
        while (ld_acquire(&g_bar2[grp]) < tgt) {}
    }
    __syncthreads();
}

// ---------------------------------------------------------------------------
// Recurrence v8. 128 CTAs x 512 threads, persistent.
// CTA cid: cols n0 = (cid&63)*16, batch half hb = cid>>6 (pairs hb*16..+15).
// Thread tid = lb + 32*ks: warp ks owns k-slice [64ks, 64ks+64);
// lane: p = lb&15 (batch pair), jh = lb>>4 (8-col half).
// Inner loop: software-pipelined blocks of 8 k — prefetch next 8 LDG.64
// while computing current 8 x (4 LDS.128 + 8 FFMA2).
// Smem: Wd[1024][16] u64 dup pairs (128KB, once), Red[8][16][32] u64 (32KB).
// ---------------------------------------------------------------------------
__global__ __launch_bounds__(512) void rnn_recurrence(
    const float* __restrict__ W_hh, float* __restrict__ states)
{
    extern __shared__ __align__(16) unsigned long long smu[];
    unsigned long long* Wd  = smu;            // [1024][16] u64   128 KB
    unsigned long long* Red = smu + RH * 16;  // [8][16][32] u64   32 KB

    const int tid = threadIdx.x;
    const int cid = blockIdx.x;
    const int n0 = (cid & 63) * 16;
    const int hb = cid >> 6;
    const int lb = tid & 31;
    const int ks = tid >> 5;
    const int p  = lb & 15;
    const int jh = lb >> 4;

    // One-time: duplicated W pairs Wd[k][j] = (W[k][n0+j], same), j = 0..15
    for (int idx = tid; idx < RH * 16; idx += 512) {
        int k = idx >> 4, j = idx & 15;
        float w = W_hh[(size_t)k * RH + n0 + j];
        Wd[idx] = pack2(w, w);
    }
    __syncthreads();

    unsigned epoch = 0;

    // t = 0: h_0 = tanh(xp). 32 b x 16 cols = 512 outputs, 1/thread.
    {
        int j = tid >> 5, b = hb * 32 + (tid & 31);
        float* op = states + (size_t)b * RH + n0 + j;
        float v = tanhf(*op);
        *op = v;
        stcg32((float*)&g_hT[0][n0 + j][0] + b, v);
    }
    grid_bar_g(&epoch, tid, hb);

    for (int t = 1; t < RT; ++t) {
        const float2* hp = &g_hT[(t - 1) & 1][ks * 64][hb * 16 + p];
        const unsigned long long* wp = Wd + (size_t)(ks * 64) * 16 + jh * 8;

        unsigned long long a[8];
#pragma unroll
        for (int c = 0; c < 8; c++) a[c] = 0ull;

        // prologue: prefetch k-block 0 (8 LDG.64 in flight)
        unsigned long long hbuf[8];
#pragma unroll
        for (int i = 0; i < 8; i++)
            hbuf[i] = ldcg64(hp + (size_t)i * 32);

#pragma unroll
        for (int blk = 0; blk < 8; blk++) {
            unsigned long long hcur[8];
#pragma unroll
            for (int i = 0; i < 8; i++) hcur[i] = hbuf[i];

            // prefetch next block while computing this one
            if (blk < 7) {
#pragma unroll
                for (int i = 0; i < 8; i++)
                    hbuf[i] = ldcg64(hp + (size_t)((blk + 1) * 8 + i) * 32);
            }

            const unsigned long long* wb = wp + (size_t)blk * 8 * 16;
#pragma unroll
            for (int i = 0; i < 8; i++) {
                ulonglong2 w01 = *(const ulonglong2*)(wb + i * 16);
                ulonglong2 w23 = *(const ulonglong2*)(wb + i * 16 + 2);
                ulonglong2 w45 = *(const ulonglong2*)(wb + i * 16 + 4);
                ulonglong2 w67 = *(const ulonglong2*)(wb + i * 16 + 6);
                unsigned long long h = hcur[i];
                a[0] = ffma2(h, w01.x, a[0]);
                a[1] = ffma2(h, w01.y, a[1]);
                a[2] = ffma2(h, w23.x, a[2]);
                a[3] = ffma2(h, w23.y, a[3]);
                a[4] = ffma2(h, w45.x, a[4]);
                a[5] = ffma2(h, w45.y, a[5]);
                a[6] = ffma2(h, w67.x, a[6]);
                a[7] = ffma2(h, w67.y, a[7]);
            }
        }

        // publish partials: Red[c][ks][lb] (STS.64, lane-contiguous)
#pragma unroll
        for (int c = 0; c < 8; c++)
            Red[(size_t)c * 512 + ks * 32 + lb] = a[c];
        __syncthreads();

        // k-reduce (16-way) + tanh epilogue: 256 threads, 1 pair-output each
        if (tid < 256) {
            const int rp = tid & 15;          // batch pair within half
            const int rj = tid >> 4;          // col 0..15
            const int rc = rj & 7;
            const int rh2 = rj >> 3;
            const unsigned long long* rsrc =
                Red + (size_t)rc * 512 + rh2 * 16 + rp;
            unsigned long long s = rsrc[0];
#pragma unroll
            for (int q = 1; q < 16; q++) s = add2(s, rsrc[(size_t)q * 32]);
            float2 f = unpack2(s);

            const int P = hb * 16 + rp;       // global pair -> batches 2P, 2P+1
            float* op0 = states + (size_t)t * (RB * RH) + (size_t)(2 * P) * RH + n0 + rj;
            float* op1 = op0 + RH;
            float v0 = tanhf(*op0 + f.x);
            float v1 = tanhf(*op1 + f.y);
            *op0 = v0;
            *op1 = v1;
            stcg64(&g_hT[t & 1][n0 + rj][P], pack2(v0, v1));
        }

        if (t < RT - 1) grid_bar_g(&epoch, tid, hb);
    }
}

// ---------------------------------------------------------------------------
extern "C" void kernel_launch(void* const* d_in, const int* in_sizes, int n_in,
                              void* d_out, int out_size)
{
    const float* X    = (const float*)d_in[0];
    const float* W_xh = (const float*)d_in[1];
    const float* W_hh = (const float*)d_in[2];
    const float* b_h  = (const float*)d_in[3];
    const float* W_hq = (const float*)d_in[4];
    const float* b_q  = (const float*)d_in[5];

    float* outputs = (float*)d_out;                      // [T*B, O]
    float* states  = outputs + (size_t)RT * RB * RO;     // [T*B, H]

    const int M = RT * RB;  // 32768
    const int rec_smem = (RH * 16 + 8 * 16 * 32) * 8;    // 128KB + 32KB

    cudaFuncSetAttribute(rnn_recurrence,
                         cudaFuncAttributeMaxDynamicSharedMemorySize, rec_smem);

    dim3 blk(256);
    dim3 g1(RH / GBN, M / GBM);   // Xproj: N=1024, K=512 (resets barrier ctrs)
    sgemm_bias<<<g1, blk>>>(X, W_xh, b_h, states, M, RH, RI, 1);

    rnn_recurrence<<<128, 512, rec_smem>>>(W_hh, states);

    dim3 g3(RO / GBN, M / GBM);   // outputs: N=512, K=1024
    sgemm_bias<<<g3, blk>>>(states, W_hq, b_q, outputs, M, RO, RH, 0);
}

// round 11
// speedup vs baseline: 1.9456x; 1.1536x over previous
#include <cuda_runtime.h>
#include <cuda_bf16.h>
#include <cstdint>

// ---------------------------------------------------------------------------
// RNN: h_t = tanh(X_t @ W_xh + b_h + h_{t-1} @ W_hh) ; y_t = h_t @ W_hq + b_q
// out = [outputs (T*B*O floats) | states (T*B*H floats)]
// T=512 B=64 H=1024 I=512 O=512
//
// R10: tcgen05 is sm_103a-only and the harness targets sm_103 -> use baseline
// warp-level tensor cores instead: mma.sync m16n8k16 bf16 with 2-term split
// (A1W1 + A1W2 + A2W1). W transposed+split once (wsplit). Recurrence = R8.
// ---------------------------------------------------------------------------

#define RT 512
#define RB 64
#define RH 1024
#define RI 512
#define RO 512

__device__ unsigned g_bar2[2];
__device__ __align__(16) float2 g_hT[2][RH][RB / 2];
// split+transposed weights: Wt[n][k] bf16
__device__ __align__(16) __nv_bfloat16 g_Wxh1t[RH * RI];
__device__ __align__(16) __nv_bfloat16 g_Wxh2t[RH * RI];
__device__ __align__(16) __nv_bfloat16 g_Whq1t[RO * RH];
__device__ __align__(16) __nv_bfloat16 g_Whq2t[RO * RH];

// ---- scalar f32x2 helpers (recurrence) ----
__device__ __forceinline__ unsigned long long ffma2(unsigned long long a,
                                                    unsigned long long b,
                                                    unsigned long long c) {
    unsigned long long d;
    asm("fma.rn.f32x2 %0, %1, %2, %3;" : "=l"(d) : "l"(a), "l"(b), "l"(c));
    return d;
}
__device__ __forceinline__ unsigned long long add2(unsigned long long a,
                                                   unsigned long long b) {
    unsigned long long d;
    asm("add.rn.f32x2 %0, %1, %2;" : "=l"(d) : "l"(a), "l"(b));
    return d;
}
__device__ __forceinline__ unsigned long long pack2(float lo, float hi) {
    unsigned long long r;
    asm("mov.b64 %0, {%1, %2};" : "=l"(r) : "f"(lo), "f"(hi));
    return r;
}
__device__ __forceinline__ float2 unpack2(unsigned long long v) {
    float lo, hi;
    asm("mov.b64 {%0, %1}, %2;" : "=f"(lo), "=f"(hi) : "l"(v));
    return make_float2(lo, hi);
}
__device__ __forceinline__ unsigned long long ldcg64(const void* p) {
    unsigned long long v;
    asm volatile("ld.global.cg.b64 %0, [%1];" : "=l"(v) : "l"(p));
    return v;
}
__device__ __forceinline__ void stcg32(float* p, float v) {
    asm volatile("st.global.cg.f32 [%0], %1;" :: "l"(p), "f"(v));
}
__device__ __forceinline__ void stcg64(void* p, unsigned long long v) {
    asm volatile("st.global.cg.b64 [%0], %1;" :: "l"(p), "l"(v));
}
__device__ __forceinline__ void red_release_add(unsigned* p, unsigned v) {
    asm volatile("red.release.gpu.global.add.u32 [%0], %1;" :: "l"(p), "r"(v)
                 : "memory");
}
__device__ __forceinline__ unsigned ld_acquire(const unsigned* p) {
    unsigned v;
    asm volatile("ld.acquire.gpu.global.u32 %0, [%1];" : "=r"(v) : "l"(p)
                 : "memory");
    return v;
}

// ---- tensor-core helpers (baseline PTX: sm_80+, valid on sm_103) ----
__device__ __forceinline__ uint32_t smem_u32(const void* p) {
    uint32_t a;
    asm("{ .reg .u64 t; cvta.to.shared.u64 t, %1; cvt.u32.u64 %0, t; }"
        : "=r"(a) : "l"(p));
    return a;
}
__device__ __forceinline__ uint32_t cvt2bf(float lo, float hi) {
    uint32_t r;
    asm("cvt.rn.bf16x2.f32 %0, %1, %2;" : "=r"(r) : "f"(hi), "f"(lo));
    return r;
}
__device__ __forceinline__ void ldm4(uint32_t* r, uint32_t addr) {
    asm volatile(
        "ldmatrix.sync.aligned.m8n8.x4.shared.b16 {%0,%1,%2,%3}, [%4];"
        : "=r"(r[0]), "=r"(r[1]), "=r"(r[2]), "=r"(r[3]) : "r"(addr));
}
__device__ __forceinline__ void mma_bf16(float* c, const uint32_t* a,
                                         uint32_t b0, uint32_t b1) {
    asm volatile(
        "mma.sync.aligned.m16n8k16.row.col.f32.bf16.bf16.f32 "
        "{%0,%1,%2,%3}, {%4,%5,%6,%7}, {%8,%9}, {%0,%1,%2,%3};"
        : "+f"(c[0]), "+f"(c[1]), "+f"(c[2]), "+f"(c[3])
        : "r"(a[0]), "r"(a[1]), "r"(a[2]), "r"(a[3]), "r"(b0), "r"(b1));
}

// ---------------------------------------------------------------------------
// wsplit: W[K,N] fp32 -> Wt1/Wt2[N,K] bf16 (transpose + 2-term split).
// ---------------------------------------------------------------------------
__global__ __launch_bounds__(256) void wsplit(
    const float* __restrict__ W, __nv_bfloat16* __restrict__ Wt1,
    __nv_bfloat16* __restrict__ Wt2, int K, int N, int reset)
{
    __shared__ float tile[32][33];
    const int tx = threadIdx.x & 31, ty = threadIdx.x >> 5;
    const int bx = blockIdx.x, by = blockIdx.y;
    if (reset && bx == 0 && by == 0 && threadIdx.x == 0) {
        g_bar2[0] = 0u;
        g_bar2[1] = 0u;
    }
    const int n = bx * 32 + tx;
#pragma unroll
    for (int i = 0; i < 4; i++) {
        int k = by * 32 + ty + i * 8;
        tile[ty + i * 8][tx] = W[(size_t)k * N + n];
    }
    __syncthreads();
    const int k2 = by * 32 + tx;
#pragma unroll
    for (int i = 0; i < 4; i++) {
        int n2 = bx * 32 + ty + i * 8;
        float v = tile[tx][ty + i * 8];
        __nv_bfloat16 b1 = __float2bfloat16_rn(v);
        float r = v - __bfloat162float(b1);
        Wt1[(size_t)n2 * K + k2] = b1;
        Wt2[(size_t)n2 * K + k2] = __float2bfloat16_rn(r);
    }
}

// ---------------------------------------------------------------------------
// mma_gemm: C[M,N] = A[M,K](fp32) @ W + bias, W as Bt1/Bt2[N,K] bf16.
// CTA tile 128x64, 256 thr = 8 warps (4m x 2n), warp 32x32, K-chunk 64.
// A split to bf16 pairs in-kernel. smem rows stride 144B (conflict-free
// ldmatrix: consecutive rows 4 banks apart). 3 products: A1B1+A1B2+A2B1.
// ---------------------------------------------------------------------------
#define AS1 0
#define AS2 18432
#define BS1 36864
#define BS2 46080
#define BIAS_OFF 55296
#define MM_SMEM 55552
#define RSTR 144            // smem row stride in bytes (72 bf16)

__global__ __launch_bounds__(256) void mma_gemm(
    const float* __restrict__ A,
    const __nv_bfloat16* __restrict__ Bt1,
    const __nv_bfloat16* __restrict__ Bt2,
    const float* __restrict__ bias, float* __restrict__ C,
    int M, int N, int K)
{
    extern __shared__ __align__(16) char ts[];
    const uint32_t sb = smem_u32(ts);
    float* sBias = (float*)(ts + BIAS_OFF);

    const int tid = threadIdx.x;
    const int wid = tid >> 5;
    const int lane = tid & 31;
    const int n0 = blockIdx.x * 64;
    const int m0 = blockIdx.y * 128;

    const int mw = (wid & 3) * 32;
    const int nw = (wid >> 2) * 32;
    const int l16 = lane & 15;
    const int lhi = lane >> 4;

    if (tid < 64) sBias[tid] = bias[n0 + tid];

    float acc[2][4][4];
#pragma unroll
    for (int i = 0; i < 2; i++)
#pragma unroll
        for (int j = 0; j < 4; j++)
#pragma unroll
            for (int q = 0; q < 4; q++) acc[i][j][q] = 0.0f;

    const int sr = tid >> 4;        // A staging row 0..15
    const int sc = tid & 15;        // A staging f4-col 0..15
    const int br = tid >> 3;        // B staging row 0..31
    const int bc = tid & 7;         // B staging u4-col 0..7

    const int nch = K >> 6;
    for (int c = 0; c < nch; ++c) {
        const int k0 = c << 6;
        if (c > 0) __syncthreads();   // WAR: previous ldmatrix reads done

        // stage A [128m][64k]: fp32 -> bf16 split pairs
#pragma unroll
        for (int it = 0; it < 8; it++) {
            int r = sr + it * 16;
            float4 v = *(const float4*)(A + (size_t)(m0 + r) * K + k0 + sc * 4);
            uint32_t p1a = cvt2bf(v.x, v.y);
            uint32_t p1b = cvt2bf(v.z, v.w);
            float fx = v.x - __uint_as_float(p1a << 16);
            float fy = v.y - __uint_as_float(p1a & 0xFFFF0000u);
            float fz = v.z - __uint_as_float(p1b << 16);
            float fw = v.w - __uint_as_float(p1b & 0xFFFF0000u);
            uint32_t p2a = cvt2bf(fx, fy);
            uint32_t p2b = cvt2bf(fz, fw);
            uint32_t off = (uint32_t)(r * RSTR + sc * 8);
            *(unsigned long long*)(ts + AS1 + off) =
                (unsigned long long)p1a | ((unsigned long long)p1b << 32);
            *(unsigned long long*)(ts + AS2 + off) =
                (unsigned long long)p2a | ((unsigned long long)p2b << 32);
        }
        // stage B [64n][64k] bf16 x 2 splits
#pragma unroll
        for (int it = 0; it < 2; it++) {
            int r = br + it * 32;
            size_t go = (size_t)(n0 + r) * K + k0 + bc * 8;
            uint4 v1 = *(const uint4*)(Bt1 + go);
            uint4 v2 = *(const uint4*)(Bt2 + go);
            uint32_t off = (uint32_t)(r * RSTR + bc * 16);
            *(uint4*)(ts + BS1 + off) = v1;
            *(uint4*)(ts + BS2 + off) = v2;
        }
        __syncthreads();

        // compute: 4 k16 steps
#pragma unroll
        for (int ks = 0; ks < 4; ks++) {
            const uint32_t kb = (uint32_t)((ks * 16 + lhi * 8) * 2);

            uint32_t a1[2][4], a2[2][4];
#pragma unroll
            for (int mf = 0; mf < 2; mf++) {
                uint32_t ao = (uint32_t)((mw + mf * 16 + l16) * RSTR) + kb;
                ldm4(a1[mf], sb + AS1 + ao);
                ldm4(a2[mf], sb + AS2 + ao);
            }
            uint32_t b1[2][4], b2[2][4];
#pragma unroll
            for (int np = 0; np < 2; np++) {
                uint32_t bo = (uint32_t)((nw + np * 16 + l16) * RSTR) + kb;
                ldm4(b1[np], sb + BS1 + bo);
                ldm4(b2[np], sb + BS2 + bo);
            }
#pragma unroll
            for (int mf = 0; mf < 2; mf++)
#pragma unroll
                for (int np = 0; np < 2; np++)
#pragma unroll
                    for (int hf = 0; hf < 2; hf++) {
                        float* cc = acc[mf][np * 2 + hf];
                        mma_bf16(cc, a1[mf], b1[np][hf], b1[np][hf + 2]);
                        mma_bf16(cc, a1[mf], b2[np][hf], b2[np][hf + 2]);
                        mma_bf16(cc, a2[mf], b1[np][hf], b1[np][hf + 2]);
                    }
        }
    }
    __syncthreads();

    // epilogue: warp 32x32 tile; lane g = lane>>2, t = lane&3
    const int g = lane >> 2;
    const int t = lane & 3;
#pragma unroll
    for (int mf = 0; mf < 2; mf++) {
#pragma unroll
        for (int nf = 0; nf < 4; nf++) {
            const int col = nw + nf * 8 + 2 * t;
            const float bx0 = sBias[col];
            const float bx1 = sBias[col + 1];
            const int row = m0 + mw + mf * 16 + g;
            float* cp = C + (size_t)row * N + n0 + col;
            float2 o0 = make_float2(acc[mf][nf][0] + bx0, acc[mf][nf][1] + bx1);
            float2 o1 = make_float2(acc[mf][nf][2] + bx0, acc[mf][nf][3] + bx1);
            *(float2*)cp = o0;
            *(float2*)(cp + (size_t)8 * N) = o1;
        }
    }
}

// ---------------------------------------------------------------------------
// Group grid barrier (R8, unchanged)
// ---------------------------------------------------------------------------
__device__ __forceinline__ void grid_bar_g(unsigned* epoch, int tid, int grp) {
    __syncthreads();
    *epoch += 1;
    if (tid == 0) {
        red_release_add(&g_bar2[grp], 1u);
        const unsigned tgt = (*epoch) * 64u;
        while (ld_acquire(&g_bar2[grp]) < tgt) {}
    }
    __syncthreads();
}

// ---------------------------------------------------------------------------
// Recurrence v8 (byte-identical to R8)
// ---------------------------------------------------------------------------
__global__ __launch_bounds__(512) void rnn_recurrence(
    const float* __restrict__ W_hh, float* __restrict__ states)
{
    extern __shared__ __align__(16) unsigned long long smu[];
    unsigned long long* Wd  = smu;            // [1024][16] u64   128 KB
    unsigned long long* Red = smu + RH * 16;  // [8][16][32] u64   32 KB

    const int tid = threadIdx.x;
    const int cid = blockIdx.x;
    const int n0 = (cid & 63) * 16;
    const int hb = cid >> 6;
    const int lb = tid & 31;
    const int ks = tid >> 5;
    const int p  = lb & 15;
    const int jh = lb >> 4;

    for (int idx = tid; idx < RH * 16; idx += 512) {
        int k = idx >> 4, j = idx & 15;
        float w = W_hh[(size_t)k * RH + n0 + j];
        Wd[idx] = pack2(w, w);
    }
    __syncthreads();

    unsigned epoch = 0;

    {
        int j = tid >> 5, b = hb * 32 + (tid & 31);
        float* op = states + (size_t)b * RH + n0 + j;
        float v = tanhf(*op);
        *op = v;
        stcg32((float*)&g_hT[0][n0 + j][0] + b, v);
    }
    grid_bar_g(&epoch, tid, hb);

    for (int t = 1; t < RT; ++t) {
        const float2* hp = &g_hT[(t - 1) & 1][ks * 64][hb * 16 + p];
        const unsigned long long* wp = Wd + (size_t)(ks * 64) * 16 + jh * 8;

        unsigned long long a[8];
#pragma unroll
        for (int c = 0; c < 8; c++) a[c] = 0ull;

        unsigned long long hbuf[8];
#pragma unroll
        for (int i = 0; i < 8; i++)
            hbuf[i] = ldcg64(hp + (size_t)i * 32);

#pragma unroll
        for (int blk = 0; blk < 8; blk++) {
            unsigned long long hcur[8];
#pragma unroll
            for (int i = 0; i < 8; i++) hcur[i] = hbuf[i];

            if (blk < 7) {
#pragma unroll
                for (int i = 0; i < 8; i++)
                    hbuf[i] = ldcg64(hp + (size_t)((blk + 1) * 8 + i) * 32);
            }

            const unsigned long long* wb = wp + (size_t)blk * 8 * 16;
#pragma unroll
            for (int i = 0; i < 8; i++) {
                ulonglong2 w01 = *(const ulonglong2*)(wb + i * 16);
                ulonglong2 w23 = *(const ulonglong2*)(wb + i * 16 + 2);
                ulonglong2 w45 = *(const ulonglong2*)(wb + i * 16 + 4);
                ulonglong2 w67 = *(const ulonglong2*)(wb + i * 16 + 6);
                unsigned long long h = hcur[i];
                a[0] = ffma2(h, w01.x, a[0]);
                a[1] = ffma2(h, w01.y, a[1]);
                a[2] = ffma2(h, w23.x, a[2]);
                a[3] = ffma2(h, w23.y, a[3]);
                a[4] = ffma2(h, w45.x, a[4]);
                a[5] = ffma2(h, w45.y, a[5]);
                a[6] = ffma2(h, w67.x, a[6]);
                a[7] = ffma2(h, w67.y, a[7]);
            }
        }

#pragma unroll
        for (int c = 0; c < 8; c++)
            Red[(size_t)c * 512 + ks * 32 + lb] = a[c];
        __syncthreads();

        if (tid < 256) {
            const int rp = tid & 15;
            const int rj = tid >> 4;
            const int rc = rj & 7;
            const int rh2 = rj >> 3;
            const unsigned long long* rsrc =
                Red + (size_t)rc * 512 + rh2 * 16 + rp;
            unsigned long long s = rsrc[0];
#pragma unroll
            for (int q = 1; q < 16; q++) s = add2(s, rsrc[(size_t)q * 32]);
            float2 f = unpack2(s);

            const int P = hb * 16 + rp;
            float* op0 = states + (size_t)t * (RB * RH) + (size_t)(2 * P) * RH + n0 + rj;
            float* op1 = op0 + RH;
            float v0 = tanhf(*op0 + f.x);
            float v1 = tanhf(*op1 + f.y);
            *op0 = v0;
            *op1 = v1;
            stcg64(&g_hT[t & 1][n0 + rj][P], pack2(v0, v1));
        }

        if (t < RT - 1) grid_bar_g(&epoch, tid, hb);
    }
}

// ---------------------------------------------------------------------------
extern "C" void kernel_launch(void* const* d_in, const int* in_sizes, int n_in,
                              void* d_out, int out_size)
{
    const float* X    = (const float*)d_in[0];
    const float* W_xh = (const float*)d_in[1];
    const float* W_hh = (const float*)d_in[2];
    const float* b_h  = (const float*)d_in[3];
    const float* W_hq = (const float*)d_in[4];
    const float* b_q  = (const float*)d_in[5];

    float* outputs = (float*)d_out;                      // [T*B, O]
    float* states  = outputs + (size_t)RT * RB * RO;     // [T*B, H]

    const int M = RT * RB;  // 32768
    const int rec_smem = (RH * 16 + 8 * 16 * 32) * 8;    // 128KB + 32KB

    __nv_bfloat16 *pWxh1, *pWxh2, *pWhq1, *pWhq2;
    cudaGetSymbolAddress((void**)&pWxh1, g_Wxh1t);
    cudaGetSymbolAddress((void**)&pWxh2, g_Wxh2t);
    cudaGetSymbolAddress((void**)&pWhq1, g_Whq1t);
    cudaGetSymbolAddress((void**)&pWhq2, g_Whq2t);

    cudaFuncSetAttribute(rnn_recurrence,
                         cudaFuncAttributeMaxDynamicSharedMemorySize, rec_smem);
    cudaFuncSetAttribute(mma_gemm,
                         cudaFuncAttributeMaxDynamicSharedMemorySize, MM_SMEM);

    // W_xh[512,1024] -> Wt[1024,512]; resets barrier counters
    wsplit<<<dim3(RH / 32, RI / 32), 256>>>(W_xh, pWxh1, pWxh2, RI, RH, 1);
    // W_hq[1024,512] -> Wt[512,1024]
    wsplit<<<dim3(RO / 32, RH / 32), 256>>>(W_hq, pWhq1, pWhq2, RH, RO, 0);

    // Xproj: states <- X @ W_xh + b_h   (M=32768, N=1024, K=512)
    mma_gemm<<<dim3(RH / 64, M / 128), 256, MM_SMEM>>>(
        X, pWxh1, pWxh2, b_h, states, M, RH, RI);

    rnn_recurrence<<<128, 512, rec_smem>>>(W_hh, states);

    // outputs <- states @ W_hq + b_q   (M=32768, N=512, K=1024)
    mma_gemm<<<dim3(RO / 64, M / 128), 256, MM_SMEM>>>(
        states, pWhq1, pWhq2, b_q, outputs, M, RO, RH);
}